// round 8
// baseline (speedup 1.0000x reference)
#include <cuda_runtime.h>
#include <cuda_fp16.h>
#include <cstdint>

// Problem constants
#define B_  4
#define T_  2048
#define C_  1024
#define H_  16
#define D_  64
#define M_  (B_ * T_)       // 8192 rows
#define QKV_N (3 * C_)      // 3072

// ---------------------------------------------------------------------------
// Scratch (device globals; no runtime allocation allowed)
// ---------------------------------------------------------------------------
__device__ __half g_xh[(size_t)M_ * C_],    g_xl[(size_t)M_ * C_];
__device__ __half g_wqh[(size_t)QKV_N * C_];
__device__ __half g_wph[(size_t)C_ * C_];
__device__ __half g_qh[(size_t)M_ * QKV_N], g_ql[(size_t)M_ * QKV_N];
__device__ __half g_ch[(size_t)M_ * C_],    g_cl[(size_t)M_ * C_];

// ---------------------------------------------------------------------------
// PTX helpers (all non-arch-gated sm_80/sm_90 instructions)
// ---------------------------------------------------------------------------
__device__ __forceinline__ uint32_t smem_u32(const void* p) {
    uint32_t a;
    asm("{ .reg .u64 t; cvta.to.shared.u64 t, %1; cvt.u32.u64 %0, t; }"
        : "=r"(a) : "l"(p));
    return a;
}
__device__ __forceinline__ void cp_async16(uint32_t s, const void* g) {
    asm volatile("cp.async.cg.shared.global [%0], [%1], 16;"
                 :: "r"(s), "l"(g) : "memory");
}
#define CP_COMMIT() asm volatile("cp.async.commit_group;" ::: "memory")
#define CP_WAIT0()  asm volatile("cp.async.wait_group 0;" ::: "memory")
#define CP_WAIT1()  asm volatile("cp.async.wait_group 1;" ::: "memory")

__device__ __forceinline__ void ldm_x4(uint32_t* r, uint32_t a) {
    asm volatile("ldmatrix.sync.aligned.m8n8.x4.shared.b16 {%0,%1,%2,%3}, [%4];"
        : "=r"(r[0]), "=r"(r[1]), "=r"(r[2]), "=r"(r[3]) : "r"(a));
}
__device__ __forceinline__ void ldm_x4_t(uint32_t* r, uint32_t a) {
    asm volatile("ldmatrix.sync.aligned.m8n8.x4.trans.shared.b16 {%0,%1,%2,%3}, [%4];"
        : "=r"(r[0]), "=r"(r[1]), "=r"(r[2]), "=r"(r[3]) : "r"(a));
}
__device__ __forceinline__ void mma_f16(float* d, const uint32_t* a, const uint32_t* b) {
    asm volatile(
        "mma.sync.aligned.m16n8k16.row.col.f32.f16.f16.f32 "
        "{%0,%1,%2,%3}, {%4,%5,%6,%7}, {%8,%9}, {%0,%1,%2,%3};"
        : "+f"(d[0]), "+f"(d[1]), "+f"(d[2]), "+f"(d[3])
        : "r"(a[0]), "r"(a[1]), "r"(a[2]), "r"(a[3]), "r"(b[0]), "r"(b[1]));
}
// pack two f32 -> f16x2 ({hi -> upper16, lo -> lower16})
__device__ __forceinline__ uint32_t pack_f16x2(float hi, float lo) {
    uint32_t d;
    asm("cvt.rn.f16x2.f32 %0, %1, %2;" : "=r"(d) : "f"(hi), "f"(lo));
    return d;
}
// unpack f16x2 -> float2 (.x = lower half, .y = upper half)
__device__ __forceinline__ float2 unpack_f16x2(uint32_t p) {
    __half2 h = *reinterpret_cast<__half2*>(&p);
    return __half22float2(h);
}

// ---------------------------------------------------------------------------
// Split fp32 -> (hi, lo) fp16   |   Convert fp32 -> fp16 (hi only, weights)
// ---------------------------------------------------------------------------
__global__ __launch_bounds__(256) void split_f16(
    const float* __restrict__ in, __half* __restrict__ hi,
    __half* __restrict__ lo, int n4)
{
    int i = blockIdx.x * blockDim.x + threadIdx.x;
    if (i >= n4) return;
    float4 v = reinterpret_cast<const float4*>(in)[i];
    uint32_t h0 = pack_f16x2(v.y, v.x);
    uint32_t h1 = pack_f16x2(v.w, v.z);
    float2 u0 = unpack_f16x2(h0);
    float2 u1 = unpack_f16x2(h1);
    uint32_t l0 = pack_f16x2(v.y - u0.y, v.x - u0.x);
    uint32_t l1 = pack_f16x2(v.w - u1.y, v.z - u1.x);
    reinterpret_cast<uint2*>(hi)[i] = make_uint2(h0, h1);
    reinterpret_cast<uint2*>(lo)[i] = make_uint2(l0, l1);
}

__global__ __launch_bounds__(256) void conv_f16(
    const float* __restrict__ in, __half* __restrict__ hi, int n4)
{
    int i = blockIdx.x * blockDim.x + threadIdx.x;
    if (i >= n4) return;
    float4 v = reinterpret_cast<const float4*>(in)[i];
    reinterpret_cast<uint2*>(hi)[i] =
        make_uint2(pack_f16x2(v.y, v.x), pack_f16x2(v.w, v.z));
}

// ---------------------------------------------------------------------------
// mma.sync fp16x2 GEMM: C[M,N] = (Ah+Al)[M,K] @ Bh[N,K]^T.
// 128x128 CTA tile, BK=32, 8 warps in 4x2 grid, warp tile 32x64
// (A dup x2, B dup x4 -> 64KB LDSM/iter vs 82KB with 2x4).
// B fragments via paired ldm_x4 (two n-chunks per instruction).
// 3-stage cp.async pipeline; 2 CTAs/SM. Stage = Ah | Al | Bh.
// SPLIT=true: write fp16 hi/lo instead of fp32.
// ---------------------------------------------------------------------------
#define TILE_B  10240                   // 128 rows * 40 b16 * 2B
#define STAGE_B (3 * TILE_B)            // 30720
#define GEMM_SMEM (3 * STAGE_B)         // 92160  (x2 CTAs = 184KB <= 228KB)

template <bool SPLIT>
__global__ __launch_bounds__(256, 2) void gemm_mma_f16x2(
    const __half* __restrict__ Ah, const __half* __restrict__ Al,
    const __half* __restrict__ Bh,
    float* __restrict__ Cf, __half* __restrict__ Ch,
    __half* __restrict__ Cl, int M, int N, int K)
{
    extern __shared__ char smc[];
    const uint32_t sbase = smem_u32(smc);
    const int tid = threadIdx.x;
    const int lid = tid & 31;
    const int wid = tid >> 5;
    const int wm  = wid >> 1;      // 0..3  (32-row slice)
    const int wn  = wid & 1;       // 0..1  (64-col slice)
    const int m0  = blockIdx.y * 128;
    const int n0  = blockIdx.x * 128;

    float acc[2][8][4];
#pragma unroll
    for (int i = 0; i < 2; i++)
#pragma unroll
        for (int j = 0; j < 8; j++)
#pragma unroll
            for (int q = 0; q < 4; q++) acc[i][j][q] = 0.f;

    // ldmatrix per-thread base offsets (b16 units within a tile)
    const int a_base = (wm * 32 + (lid & 15)) * 40 + ((lid >> 4) * 8);
    const int b_base = (wn * 64 + (lid & 15)) * 40 + ((lid >> 4) * 8);
    const int NS = K / 32;

#define ISSUE_STAGE(S)                                                          \
    do {                                                                        \
        const int _kc = (S) * 32;                                               \
        const uint32_t _sb = sbase + ((S) % 3) * STAGE_B;                       \
        _Pragma("unroll")                                                       \
        for (int _r = 0; _r < 2; _r++) {                                        \
            const int _c   = tid + _r * 256;                                    \
            const int _row = _c >> 2;                                           \
            const int _c8  = (_c & 3) * 8;                                      \
            const uint32_t _so = _sb + (uint32_t)((_row * 40 + _c8) * 2);       \
            const size_t _ga = (size_t)(m0 + _row) * K + _kc + _c8;             \
            const size_t _gb = (size_t)(n0 + _row) * K + _kc + _c8;             \
            cp_async16(_so,              Ah + _ga);                             \
            cp_async16(_so + TILE_B,     Al + _ga);                             \
            cp_async16(_so + 2 * TILE_B, Bh + _gb);                             \
        }                                                                       \
        CP_COMMIT();                                                            \
    } while (0)

    ISSUE_STAGE(0);
    ISSUE_STAGE(1);

    for (int s = 0; s < NS; s++) {
        if (s < NS - 1) CP_WAIT1();
        else            CP_WAIT0();
        __syncthreads();
        if (s + 2 < NS) ISSUE_STAGE(s + 2);

        const uint32_t sb = sbase + (s % 3) * STAGE_B;
#pragma unroll
        for (int ks = 0; ks < 2; ks++) {
            uint32_t ah[2][4], al[2][4], bh[8][2];
#pragma unroll
            for (int mi = 0; mi < 2; mi++) {
                const uint32_t ao = sb +
                    (uint32_t)((a_base + mi * 16 * 40 + ks * 16) * 2);
                ldm_x4(ah[mi], ao);
                ldm_x4(al[mi], ao + TILE_B);
            }
            // B: 4 x ldm_x4, each covering two adjacent 8-col n-chunks
#pragma unroll
            for (int nb = 0; nb < 4; nb++) {
                uint32_t bfr[4];
                const uint32_t bo = sb + 2 * TILE_B +
                    (uint32_t)((b_base + nb * 16 * 40 + ks * 16) * 2);
                ldm_x4(bfr, bo);
                bh[2 * nb][0]     = bfr[0];
                bh[2 * nb][1]     = bfr[2];
                bh[2 * nb + 1][0] = bfr[1];
                bh[2 * nb + 1][1] = bfr[3];
            }
            // 2 passes: same accumulator revisited at distance 16
#pragma unroll
            for (int mi = 0; mi < 2; mi++)
#pragma unroll
                for (int ni = 0; ni < 8; ni++)
                    mma_f16(acc[mi][ni], ah[mi], bh[ni]);
#pragma unroll
            for (int mi = 0; mi < 2; mi++)
#pragma unroll
                for (int ni = 0; ni < 8; ni++)
                    mma_f16(acc[mi][ni], al[mi], bh[ni]);
        }
    }
#undef ISSUE_STAGE

#pragma unroll
    for (int mi = 0; mi < 2; mi++)
#pragma unroll
        for (int ni = 0; ni < 8; ni++) {
            const int row = m0 + wm * 32 + mi * 16 + (lid >> 2);
            const int col = n0 + wn * 64 + ni * 8 + (lid & 3) * 2;
            if (SPLIT) {
                uint32_t h0 = pack_f16x2(acc[mi][ni][1], acc[mi][ni][0]);
                uint32_t h1 = pack_f16x2(acc[mi][ni][3], acc[mi][ni][2]);
                float2 u0 = unpack_f16x2(h0);
                float2 u1 = unpack_f16x2(h1);
                uint32_t l0 = pack_f16x2(acc[mi][ni][1] - u0.y,
                                         acc[mi][ni][0] - u0.x);
                uint32_t l1 = pack_f16x2(acc[mi][ni][3] - u1.y,
                                         acc[mi][ni][2] - u1.x);
                *reinterpret_cast<uint32_t*>(&Ch[(size_t)row * N + col])       = h0;
                *reinterpret_cast<uint32_t*>(&Ch[(size_t)(row + 8) * N + col]) = h1;
                *reinterpret_cast<uint32_t*>(&Cl[(size_t)row * N + col])       = l0;
                *reinterpret_cast<uint32_t*>(&Cl[(size_t)(row + 8) * N + col]) = l1;
            } else {
                float2 v0 = make_float2(acc[mi][ni][0], acc[mi][ni][1]);
                float2 v1 = make_float2(acc[mi][ni][2], acc[mi][ni][3]);
                *reinterpret_cast<float2*>(&Cf[(size_t)row * N + col])       = v0;
                *reinterpret_cast<float2*>(&Cf[(size_t)(row + 8) * N + col]) = v1;
            }
        }
}

// ---------------------------------------------------------------------------
// Tensor-core causal flash attention, fp16x2 split precision (unchanged).
// CTA: 256 thr (8 warps), 128-row Q tile per CTA. K/V 64-row hi-only tiles,
// 3-stage cp.async pipeline. Warp w owns Q rows [16w,16w+16).
// Q split hi/lo; K,V rounded to fp16 (error ~2^-12, under tolerance).
// ---------------------------------------------------------------------------
#define AKT_B   9216                 // 64 rows * 72 b16 * 2B
#define ASTG_B  (2 * AKT_B)          // Kh | Vh
#define ATT_SMEM (3 * ASTG_B)        // 55296

__global__ __launch_bounds__(256) void attn_mma(
    const __half* __restrict__ qh_g, const __half* __restrict__ ql_g,
    __half* __restrict__ ch_g, __half* __restrict__ cl_g)
{
    extern __shared__ char smc[];
    const uint32_t abase = smem_u32(smc);
    const int tid = threadIdx.x;
    const int lid = tid & 31;
    const int wid = tid >> 5;
    const int qi  = (int)gridDim.x - 1 - (int)blockIdx.x;  // long CTAs first
    const int bh  = blockIdx.y;
    const int b   = bh >> 4;
    const int h   = bh & 15;
    const int q0  = qi * 128;
    const int bT0 = b * T_;
    const int nkt = 2 * qi + 2;

    // ---- Q fragments (hi/lo), loaded once from global ----
    uint32_t qfh[4][4], qfl[4][4];
    {
        const int r0 = bT0 + q0 + wid * 16 + (lid >> 2);
#pragma unroll
        for (int kc = 0; kc < 4; kc++) {
            const int c0 = h * 64 + kc * 16 + (lid & 3) * 2;
            const size_t o00 = (size_t)r0 * QKV_N + c0;
            const size_t o10 = o00 + 8 * QKV_N;
            qfh[kc][0] = *reinterpret_cast<const uint32_t*>(qh_g + o00);
            qfh[kc][1] = *reinterpret_cast<const uint32_t*>(qh_g + o10);
            qfh[kc][2] = *reinterpret_cast<const uint32_t*>(qh_g + o00 + 8);
            qfh[kc][3] = *reinterpret_cast<const uint32_t*>(qh_g + o10 + 8);
            qfl[kc][0] = *reinterpret_cast<const uint32_t*>(ql_g + o00);
            qfl[kc][1] = *reinterpret_cast<const uint32_t*>(ql_g + o10);
            qfl[kc][2] = *reinterpret_cast<const uint32_t*>(ql_g + o00 + 8);
            qfl[kc][3] = *reinterpret_cast<const uint32_t*>(ql_g + o10 + 8);
        }
    }

    float o[8][4];
#pragma unroll
    for (int j = 0; j < 8; j++)
#pragma unroll
        for (int q = 0; q < 4; q++) o[j][q] = 0.f;
    float m0r = -1e30f, m1r = -1e30f, l0r = 0.f, l1r = 0.f;

    // K/V hi-only tile loader: 2 tiles x 64 rows x 8 groups = 1024 jobs
#define ISSUE_KT(KT)                                                            \
    do {                                                                        \
        const uint32_t _sb = abase + ((KT) % 3) * ASTG_B;                       \
        const int _kv0 = (KT) * 64;                                             \
        _Pragma("unroll")                                                       \
        for (int _r = 0; _r < 4; _r++) {                                        \
            const int _j    = tid + _r * 256;                                   \
            const int _tile = _j >> 9;                                          \
            const int _rem  = _j & 511;                                         \
            const int _row  = _rem >> 3;                                        \
            const int _g    = _rem & 7;                                         \
            const size_t _go = (size_t)(bT0 + _kv0 + _row) * QKV_N              \
                               + C_ * (1 + _tile) + h * 64 + _g * 8;            \
            cp_async16(_sb + _tile * AKT_B + (uint32_t)(_row * 144 + _g * 16),  \
                       qh_g + _go);                                             \
        }                                                                       \
        CP_COMMIT();                                                            \
    } while (0)

    ISSUE_KT(0);
    ISSUE_KT(1);   // nkt >= 2 always

    const int qrow0 = q0 + wid * 16 + (lid >> 2);   // global q row (half 0)
    const int qrow1 = qrow0 + 8;

    for (int kt = 0; kt < nkt; kt++) {
        if (kt < nkt - 1) CP_WAIT1();
        else              CP_WAIT0();
        __syncthreads();
        if (kt + 2 < nkt) ISSUE_KT(kt + 2);

        const uint32_t sb = abase + (kt % 3) * ASTG_B;
        const int kv0 = kt * 64;

        // ---- S = (Qh+Ql) @ Kh^T ----
        float s[8][4];
#pragma unroll
        for (int jn = 0; jn < 8; jn++) {
#pragma unroll
            for (int q = 0; q < 4; q++) s[jn][q] = 0.f;
            const uint32_t aK = sb +
                (uint32_t)(((jn * 8 + (lid & 7)) * 72 + (lid >> 3) * 8) * 2);
            uint32_t khA[4], khB[4];
            ldm_x4(khA, aK);
            ldm_x4(khB, aK + 64);
            mma_f16(s[jn], qfh[0], &khA[0]);
            mma_f16(s[jn], qfh[1], &khA[2]);
            mma_f16(s[jn], qfh[2], &khB[0]);
            mma_f16(s[jn], qfh[3], &khB[2]);
            mma_f16(s[jn], qfl[0], &khA[0]);
            mma_f16(s[jn], qfl[1], &khA[2]);
            mma_f16(s[jn], qfl[2], &khB[0]);
            mma_f16(s[jn], qfl[3], &khB[2]);
        }

        // scale + causal mask (only the last two ktiles can cross diagonal)
        const bool need_mask = (kt >= nkt - 2);
#pragma unroll
        for (int jn = 0; jn < 8; jn++) {
#pragma unroll
            for (int q = 0; q < 4; q++) s[jn][q] *= 0.125f;
            if (need_mask) {
                const int c = kv0 + jn * 8 + (lid & 3) * 2;
                if (c > qrow0)     s[jn][0] = -1e30f;
                if (c + 1 > qrow0) s[jn][1] = -1e30f;
                if (c > qrow1)     s[jn][2] = -1e30f;
                if (c + 1 > qrow1) s[jn][3] = -1e30f;
            }
        }

        // ---- online softmax (rows qrow0, qrow1 per thread) ----
        float mx0 = s[0][0], mx1 = s[0][2];
#pragma unroll
        for (int jn = 0; jn < 8; jn++) {
            mx0 = fmaxf(mx0, fmaxf(s[jn][0], s[jn][1]));
            mx1 = fmaxf(mx1, fmaxf(s[jn][2], s[jn][3]));
        }
        mx0 = fmaxf(mx0, __shfl_xor_sync(0xffffffffu, mx0, 1));
        mx0 = fmaxf(mx0, __shfl_xor_sync(0xffffffffu, mx0, 2));
        mx1 = fmaxf(mx1, __shfl_xor_sync(0xffffffffu, mx1, 1));
        mx1 = fmaxf(mx1, __shfl_xor_sync(0xffffffffu, mx1, 2));
        const float mn0 = fmaxf(m0r, mx0);
        const float mn1 = fmaxf(m1r, mx1);
        const float cr0 = __expf(m0r - mn0);
        const float cr1 = __expf(m1r - mn1);
        float sm0 = 0.f, sm1 = 0.f;
#pragma unroll
        for (int jn = 0; jn < 8; jn++) {
            s[jn][0] = __expf(s[jn][0] - mn0);
            s[jn][1] = __expf(s[jn][1] - mn0);
            s[jn][2] = __expf(s[jn][2] - mn1);
            s[jn][3] = __expf(s[jn][3] - mn1);
            sm0 += s[jn][0] + s[jn][1];
            sm1 += s[jn][2] + s[jn][3];
        }
        sm0 += __shfl_xor_sync(0xffffffffu, sm0, 1);
        sm0 += __shfl_xor_sync(0xffffffffu, sm0, 2);
        sm1 += __shfl_xor_sync(0xffffffffu, sm1, 1);
        sm1 += __shfl_xor_sync(0xffffffffu, sm1, 2);
        l0r = l0r * cr0 + sm0;
        l1r = l1r * cr1 + sm1;
        m0r = mn0; m1r = mn1;
#pragma unroll
        for (int j = 0; j < 8; j++) {
            o[j][0] *= cr0; o[j][1] *= cr0;
            o[j][2] *= cr1; o[j][3] *= cr1;
        }

        // ---- P -> fp16 hi/lo A-fragments ----
        uint32_t ph[4][4], pl[4][4];
#pragma unroll
        for (int t = 0; t < 4; t++) {
            ph[t][0] = pack_f16x2(s[2 * t][1], s[2 * t][0]);
            ph[t][1] = pack_f16x2(s[2 * t][3], s[2 * t][2]);
            ph[t][2] = pack_f16x2(s[2 * t + 1][1], s[2 * t + 1][0]);
            ph[t][3] = pack_f16x2(s[2 * t + 1][3], s[2 * t + 1][2]);
            float2 u0 = unpack_f16x2(ph[t][0]);
            float2 u1 = unpack_f16x2(ph[t][1]);
            float2 u2 = unpack_f16x2(ph[t][2]);
            float2 u3 = unpack_f16x2(ph[t][3]);
            pl[t][0] = pack_f16x2(s[2 * t][1] - u0.y,     s[2 * t][0] - u0.x);
            pl[t][1] = pack_f16x2(s[2 * t][3] - u1.y,     s[2 * t][2] - u1.x);
            pl[t][2] = pack_f16x2(s[2 * t + 1][1] - u2.y, s[2 * t + 1][0] - u2.x);
            pl[t][3] = pack_f16x2(s[2 * t + 1][3] - u3.y, s[2 * t + 1][2] - u3.x);
        }

        // ---- O += (Ph+Pl) @ Vh ----
        const uint32_t vb = sb + AKT_B;
#pragma unroll
        for (int jp = 0; jp < 4; jp++) {
#pragma unroll
            for (int kc = 0; kc < 4; kc++) {
                const uint32_t aV = vb + (uint32_t)((
                    (kc * 16 + ((lid >> 3) & 1) * 8 + (lid & 7)) * 72 +
                    jp * 16 + (lid >> 4) * 8) * 2);
                uint32_t vh[4];
                ldm_x4_t(vh, aV);
                mma_f16(o[2 * jp],     ph[kc], &vh[0]);
                mma_f16(o[2 * jp + 1], ph[kc], &vh[2]);
                mma_f16(o[2 * jp],     pl[kc], &vh[0]);
                mma_f16(o[2 * jp + 1], pl[kc], &vh[2]);
            }
        }
    }
#undef ISSUE_KT

    // ---- epilogue: normalize, split to fp16 hi/lo, write ch/cl ----
    const float inv0 = 1.f / l0r;
    const float inv1 = 1.f / l1r;
    const size_t r0 = (size_t)(bT0 + qrow0) * C_;
    const size_t r1 = (size_t)(bT0 + qrow1) * C_;
#pragma unroll
    for (int jn = 0; jn < 8; jn++) {
        const int col = h * 64 + jn * 8 + (lid & 3) * 2;
        float e0 = o[jn][0] * inv0, e1 = o[jn][1] * inv0;
        float e2 = o[jn][2] * inv1, e3 = o[jn][3] * inv1;
        uint32_t h0 = pack_f16x2(e1, e0);
        uint32_t h1 = pack_f16x2(e3, e2);
        float2 u0 = unpack_f16x2(h0);
        float2 u1 = unpack_f16x2(h1);
        uint32_t l0 = pack_f16x2(e1 - u0.y, e0 - u0.x);
        uint32_t l1 = pack_f16x2(e3 - u1.y, e2 - u1.x);
        *reinterpret_cast<uint32_t*>(&ch_g[r0 + col]) = h0;
        *reinterpret_cast<uint32_t*>(&ch_g[r1 + col]) = h1;
        *reinterpret_cast<uint32_t*>(&cl_g[r0 + col]) = l0;
        *reinterpret_cast<uint32_t*>(&cl_g[r1 + col]) = l1;
    }
}

// ---------------------------------------------------------------------------
// kernel_launch
// ---------------------------------------------------------------------------
extern "C" void kernel_launch(void* const* d_in, const int* in_sizes, int n_in,
                              void* d_out, int out_size)
{
    const float* x      = (const float*)d_in[0];  // [B,T,C]
    const float* w_qkv  = (const float*)d_in[1];  // [3C,C]
    const float* w_proj = (const float*)d_in[2];  // [C,C]
    float* out = (float*)d_out;                   // [B,T,C]

    __half *xh, *xl, *wqh, *wph, *qh, *ql, *ch, *cl;
    cudaGetSymbolAddress((void**)&xh,  g_xh);
    cudaGetSymbolAddress((void**)&xl,  g_xl);
    cudaGetSymbolAddress((void**)&wqh, g_wqh);
    cudaGetSymbolAddress((void**)&wph, g_wph);
    cudaGetSymbolAddress((void**)&qh,  g_qh);
    cudaGetSymbolAddress((void**)&ql,  g_ql);
    cudaGetSymbolAddress((void**)&ch,  g_ch);
    cudaGetSymbolAddress((void**)&cl,  g_cl);

    cudaFuncSetAttribute(gemm_mma_f16x2<true>,
                         cudaFuncAttributeMaxDynamicSharedMemorySize, GEMM_SMEM);
    cudaFuncSetAttribute(gemm_mma_f16x2<false>,
                         cudaFuncAttributeMaxDynamicSharedMemorySize, GEMM_SMEM);
    cudaFuncSetAttribute(attn_mma,
                         cudaFuncAttributeMaxDynamicSharedMemorySize, ATT_SMEM);

    // Splits / converts
    split_f16<<<(M_ * C_ / 4 + 255) / 256, 256>>>(x, xh, xl, M_ * C_ / 4);
    conv_f16<<<(QKV_N * C_ / 4 + 255) / 256, 256>>>(w_qkv, wqh, QKV_N * C_ / 4);
    conv_f16<<<(C_ * C_ / 4 + 255) / 256, 256>>>(w_proj, wph, C_ * C_ / 4);

    // 1) QKV projection -> split fp16 output (qh/ql)
    dim3 g1(QKV_N / 128, M_ / 128);
    gemm_mma_f16x2<true><<<g1, 256, GEMM_SMEM>>>(
        xh, xl, wqh, nullptr, qh, ql, M_, QKV_N, C_);

    // 2) Tensor-core causal flash attention -> split fp16 ctx (ch/cl)
    dim3 g2(T_ / 128, B_ * H_);
    attn_mma<<<g2, 256, ATT_SMEM>>>(qh, ql, ch, cl);

    // 3) Output projection -> fp32 out
    dim3 g3(C_ / 128, M_ / 128);
    gemm_mma_f16x2<false><<<g3, 256, GEMM_SMEM>>>(
        ch, cl, wph, out, nullptr, nullptr, M_, C_, C_);
}

// round 9
// speedup vs baseline: 1.1728x; 1.1728x over previous
#include <cuda_runtime.h>
#include <cuda_fp16.h>
#include <cstdint>

// Problem constants
#define B_  4
#define T_  2048
#define C_  1024
#define H_  16
#define D_  64
#define M_  (B_ * T_)       // 8192 rows
#define QKV_N (3 * C_)      // 3072

// ---------------------------------------------------------------------------
// Scratch (device globals; no runtime allocation allowed)
// ---------------------------------------------------------------------------
__device__ __half g_xh[(size_t)M_ * C_],    g_xl[(size_t)M_ * C_];
__device__ __half g_wqh[(size_t)QKV_N * C_];
__device__ __half g_wph[(size_t)C_ * C_];
__device__ __half g_qh[(size_t)M_ * QKV_N], g_ql[(size_t)M_ * QKV_N];
__device__ __half g_ch[(size_t)M_ * C_],    g_cl[(size_t)M_ * C_];

// ---------------------------------------------------------------------------
// PTX helpers (all non-arch-gated sm_80/sm_90 instructions)
// ---------------------------------------------------------------------------
__device__ __forceinline__ uint32_t smem_u32(const void* p) {
    uint32_t a;
    asm("{ .reg .u64 t; cvta.to.shared.u64 t, %1; cvt.u32.u64 %0, t; }"
        : "=r"(a) : "l"(p));
    return a;
}
__device__ __forceinline__ void cp_async16(uint32_t s, const void* g) {
    asm volatile("cp.async.cg.shared.global [%0], [%1], 16;"
                 :: "r"(s), "l"(g) : "memory");
}
#define CP_COMMIT() asm volatile("cp.async.commit_group;" ::: "memory")
#define CP_WAIT0()  asm volatile("cp.async.wait_group 0;" ::: "memory")
#define CP_WAIT1()  asm volatile("cp.async.wait_group 1;" ::: "memory")

__device__ __forceinline__ void ldm_x4(uint32_t* r, uint32_t a) {
    asm volatile("ldmatrix.sync.aligned.m8n8.x4.shared.b16 {%0,%1,%2,%3}, [%4];"
        : "=r"(r[0]), "=r"(r[1]), "=r"(r[2]), "=r"(r[3]) : "r"(a));
}
__device__ __forceinline__ void ldm_x4_t(uint32_t* r, uint32_t a) {
    asm volatile("ldmatrix.sync.aligned.m8n8.x4.trans.shared.b16 {%0,%1,%2,%3}, [%4];"
        : "=r"(r[0]), "=r"(r[1]), "=r"(r[2]), "=r"(r[3]) : "r"(a));
}
__device__ __forceinline__ void mma_f16(float* d, const uint32_t* a, const uint32_t* b) {
    asm volatile(
        "mma.sync.aligned.m16n8k16.row.col.f32.f16.f16.f32 "
        "{%0,%1,%2,%3}, {%4,%5,%6,%7}, {%8,%9}, {%0,%1,%2,%3};"
        : "+f"(d[0]), "+f"(d[1]), "+f"(d[2]), "+f"(d[3])
        : "r"(a[0]), "r"(a[1]), "r"(a[2]), "r"(a[3]), "r"(b[0]), "r"(b[1]));
}
// pack two f32 -> f16x2 ({hi -> upper16, lo -> lower16})
__device__ __forceinline__ uint32_t pack_f16x2(float hi, float lo) {
    uint32_t d;
    asm("cvt.rn.f16x2.f32 %0, %1, %2;" : "=r"(d) : "f"(hi), "f"(lo));
    return d;
}
// unpack f16x2 -> float2 (.x = lower half, .y = upper half)
__device__ __forceinline__ float2 unpack_f16x2(uint32_t p) {
    __half2 h = *reinterpret_cast<__half2*>(&p);
    return __half22float2(h);
}

// ---------------------------------------------------------------------------
// Split fp32 -> (hi, lo) fp16   |   Convert fp32 -> fp16 (hi only, weights)
// ---------------------------------------------------------------------------
__global__ __launch_bounds__(256) void split_f16(
    const float* __restrict__ in, __half* __restrict__ hi,
    __half* __restrict__ lo, int n4)
{
    int i = blockIdx.x * blockDim.x + threadIdx.x;
    if (i >= n4) return;
    float4 v = reinterpret_cast<const float4*>(in)[i];
    uint32_t h0 = pack_f16x2(v.y, v.x);
    uint32_t h1 = pack_f16x2(v.w, v.z);
    float2 u0 = unpack_f16x2(h0);
    float2 u1 = unpack_f16x2(h1);
    uint32_t l0 = pack_f16x2(v.y - u0.y, v.x - u0.x);
    uint32_t l1 = pack_f16x2(v.w - u1.y, v.z - u1.x);
    reinterpret_cast<uint2*>(hi)[i] = make_uint2(h0, h1);
    reinterpret_cast<uint2*>(lo)[i] = make_uint2(l0, l1);
}

__global__ __launch_bounds__(256) void conv_f16(
    const float* __restrict__ in, __half* __restrict__ hi, int n4)
{
    int i = blockIdx.x * blockDim.x + threadIdx.x;
    if (i >= n4) return;
    float4 v = reinterpret_cast<const float4*>(in)[i];
    reinterpret_cast<uint2*>(hi)[i] =
        make_uint2(pack_f16x2(v.y, v.x), pack_f16x2(v.w, v.z));
}

// ---------------------------------------------------------------------------
// mma.sync fp16x2 GEMM: C[M,N] = (Ah+Al)[M,K] @ Bh[N,K]^T.
// 128x128 CTA tile, BK=32, 8 warps (2x4), warp tile 64x32 (round-7 layout).
// B fragments via paired ldm_x4 with mma-operand-ordered lane mapping.
// 3-stage cp.async pipeline; 2 CTAs/SM. Stage = Ah | Al | Bh.
// SPLIT=true: write fp16 hi/lo instead of fp32.
// ---------------------------------------------------------------------------
#define TILE_B  10240                   // 128 rows * 40 b16 * 2B
#define STAGE_B (3 * TILE_B)            // 30720
#define GEMM_SMEM (3 * STAGE_B)         // 92160  (x2 CTAs = 184KB <= 228KB)

template <bool SPLIT>
__global__ __launch_bounds__(256, 2) void gemm_mma_f16x2(
    const __half* __restrict__ Ah, const __half* __restrict__ Al,
    const __half* __restrict__ Bh,
    float* __restrict__ Cf, __half* __restrict__ Ch,
    __half* __restrict__ Cl, int M, int N, int K)
{
    extern __shared__ char smc[];
    const uint32_t sbase = smem_u32(smc);
    const int tid = threadIdx.x;
    const int lid = tid & 31;
    const int wid = tid >> 5;
    const int wm  = wid >> 2;      // 0..1
    const int wn  = wid & 3;       // 0..3
    const int m0  = blockIdx.y * 128;
    const int n0  = blockIdx.x * 128;

    float acc[4][4][4];
#pragma unroll
    for (int i = 0; i < 4; i++)
#pragma unroll
        for (int j = 0; j < 4; j++)
#pragma unroll
            for (int q = 0; q < 4; q++) acc[i][j][q] = 0.f;

    // ldmatrix per-thread base offsets (b16 units within a tile)
    const int a_base = (wm * 64 + (lid & 15)) * 40 + ((lid >> 4) * 8);
    // B paired-x4 mapping: matrices [n0k0, n0k1, n1k0, n1k1]
    //   n row = wn*32 + (lid&7) + (lid>>4)*8 ; k half = ((lid>>3)&1)*8
    const int b_base = (wn * 32 + (lid & 7) + ((lid >> 4) * 8)) * 40 +
                       (((lid >> 3) & 1) * 8);
    const int NS = K / 32;

#define ISSUE_STAGE(S)                                                          \
    do {                                                                        \
        const int _kc = (S) * 32;                                               \
        const uint32_t _sb = sbase + ((S) % 3) * STAGE_B;                       \
        _Pragma("unroll")                                                       \
        for (int _r = 0; _r < 2; _r++) {                                        \
            const int _c   = tid + _r * 256;                                    \
            const int _row = _c >> 2;                                           \
            const int _c8  = (_c & 3) * 8;                                      \
            const uint32_t _so = _sb + (uint32_t)((_row * 40 + _c8) * 2);       \
            const size_t _ga = (size_t)(m0 + _row) * K + _kc + _c8;             \
            const size_t _gb = (size_t)(n0 + _row) * K + _kc + _c8;             \
            cp_async16(_so,              Ah + _ga);                             \
            cp_async16(_so + TILE_B,     Al + _ga);                             \
            cp_async16(_so + 2 * TILE_B, Bh + _gb);                             \
        }                                                                       \
        CP_COMMIT();                                                            \
    } while (0)

    ISSUE_STAGE(0);
    ISSUE_STAGE(1);

    for (int s = 0; s < NS; s++) {
        if (s < NS - 1) CP_WAIT1();
        else            CP_WAIT0();
        __syncthreads();
        if (s + 2 < NS) ISSUE_STAGE(s + 2);

        const uint32_t sb = sbase + (s % 3) * STAGE_B;
#pragma unroll
        for (int ks = 0; ks < 2; ks++) {
            uint32_t ah[4][4], al[4][4], b01[4], b23[4];
#pragma unroll
            for (int mi = 0; mi < 4; mi++) {
                const uint32_t ao = sb +
                    (uint32_t)((a_base + mi * 16 * 40 + ks * 16) * 2);
                ldm_x4(ah[mi], ao);
                ldm_x4(al[mi], ao + TILE_B);
            }
            {
                const uint32_t bo = sb + 2 * TILE_B +
                    (uint32_t)((b_base + ks * 16) * 2);
                ldm_x4(b01, bo);                       // n-chunks 0,1
                ldm_x4(b23, bo + 16 * 40 * 2);         // n-chunks 2,3
            }
            // 2 passes: same accumulator revisited at distance 16
#pragma unroll
            for (int mi = 0; mi < 4; mi++) {
                mma_f16(acc[mi][0], ah[mi], &b01[0]);
                mma_f16(acc[mi][1], ah[mi], &b01[2]);
                mma_f16(acc[mi][2], ah[mi], &b23[0]);
                mma_f16(acc[mi][3], ah[mi], &b23[2]);
            }
#pragma unroll
            for (int mi = 0; mi < 4; mi++) {
                mma_f16(acc[mi][0], al[mi], &b01[0]);
                mma_f16(acc[mi][1], al[mi], &b01[2]);
                mma_f16(acc[mi][2], al[mi], &b23[0]);
                mma_f16(acc[mi][3], al[mi], &b23[2]);
            }
        }
    }
#undef ISSUE_STAGE

#pragma unroll
    for (int mi = 0; mi < 4; mi++)
#pragma unroll
        for (int ni = 0; ni < 4; ni++) {
            const int row = m0 + wm * 64 + mi * 16 + (lid >> 2);
            const int col = n0 + wn * 32 + ni * 8 + (lid & 3) * 2;
            if (SPLIT) {
                uint32_t h0 = pack_f16x2(acc[mi][ni][1], acc[mi][ni][0]);
                uint32_t h1 = pack_f16x2(acc[mi][ni][3], acc[mi][ni][2]);
                float2 u0 = unpack_f16x2(h0);
                float2 u1 = unpack_f16x2(h1);
                uint32_t l0 = pack_f16x2(acc[mi][ni][1] - u0.y,
                                         acc[mi][ni][0] - u0.x);
                uint32_t l1 = pack_f16x2(acc[mi][ni][3] - u1.y,
                                         acc[mi][ni][2] - u1.x);
                *reinterpret_cast<uint32_t*>(&Ch[(size_t)row * N + col])       = h0;
                *reinterpret_cast<uint32_t*>(&Ch[(size_t)(row + 8) * N + col]) = h1;
                *reinterpret_cast<uint32_t*>(&Cl[(size_t)row * N + col])       = l0;
                *reinterpret_cast<uint32_t*>(&Cl[(size_t)(row + 8) * N + col]) = l1;
            } else {
                float2 v0 = make_float2(acc[mi][ni][0], acc[mi][ni][1]);
                float2 v1 = make_float2(acc[mi][ni][2], acc[mi][ni][3]);
                *reinterpret_cast<float2*>(&Cf[(size_t)row * N + col])       = v0;
                *reinterpret_cast<float2*>(&Cf[(size_t)(row + 8) * N + col]) = v1;
            }
        }
}

// ---------------------------------------------------------------------------
// Tensor-core causal flash attention, fp16x2 split precision.
// CTA: 128 thr (4 warps), 64-row Q tile per CTA -> ~3 CTAs/SM (vs 1 before).
// K/V 64-row hi-only tiles, 3-stage cp.async pipeline.
// Warp w owns Q rows [16w,16w+16). Q split hi/lo; K,V rounded to fp16.
// ---------------------------------------------------------------------------
#define AKT_B   9216                 // 64 rows * 72 b16 * 2B
#define ASTG_B  (2 * AKT_B)          // Kh | Vh
#define ATT_SMEM (3 * ASTG_B)        // 55296 (x3 CTAs = 166KB <= 228KB)

__global__ __launch_bounds__(128, 3) void attn_mma(
    const __half* __restrict__ qh_g, const __half* __restrict__ ql_g,
    __half* __restrict__ ch_g, __half* __restrict__ cl_g)
{
    extern __shared__ char smc[];
    const uint32_t abase = smem_u32(smc);
    const int tid = threadIdx.x;
    const int lid = tid & 31;
    const int wid = tid >> 5;
    const int qi  = (int)gridDim.x - 1 - (int)blockIdx.x;  // long CTAs first
    const int bh  = blockIdx.y;
    const int b   = bh >> 4;
    const int h   = bh & 15;
    const int q0  = qi * 64;
    const int bT0 = b * T_;
    const int nkt = qi + 1;

    // ---- Q fragments (hi/lo), loaded once from global ----
    uint32_t qfh[4][4], qfl[4][4];
    {
        const int r0 = bT0 + q0 + wid * 16 + (lid >> 2);
#pragma unroll
        for (int kc = 0; kc < 4; kc++) {
            const int c0 = h * 64 + kc * 16 + (lid & 3) * 2;
            const size_t o00 = (size_t)r0 * QKV_N + c0;
            const size_t o10 = o00 + 8 * QKV_N;
            qfh[kc][0] = *reinterpret_cast<const uint32_t*>(qh_g + o00);
            qfh[kc][1] = *reinterpret_cast<const uint32_t*>(qh_g + o10);
            qfh[kc][2] = *reinterpret_cast<const uint32_t*>(qh_g + o00 + 8);
            qfh[kc][3] = *reinterpret_cast<const uint32_t*>(qh_g + o10 + 8);
            qfl[kc][0] = *reinterpret_cast<const uint32_t*>(ql_g + o00);
            qfl[kc][1] = *reinterpret_cast<const uint32_t*>(ql_g + o10);
            qfl[kc][2] = *reinterpret_cast<const uint32_t*>(ql_g + o00 + 8);
            qfl[kc][3] = *reinterpret_cast<const uint32_t*>(ql_g + o10 + 8);
        }
    }

    float o[8][4];
#pragma unroll
    for (int j = 0; j < 8; j++)
#pragma unroll
        for (int q = 0; q < 4; q++) o[j][q] = 0.f;
    float m0r = -1e30f, m1r = -1e30f, l0r = 0.f, l1r = 0.f;

    // K/V hi-only tile loader: 2 tiles x 64 rows x 8 groups = 1024 jobs / 128 thr
#define ISSUE_KT(KT)                                                            \
    do {                                                                        \
        const uint32_t _sb = abase + ((KT) % 3) * ASTG_B;                       \
        const int _kv0 = (KT) * 64;                                             \
        _Pragma("unroll")                                                       \
        for (int _r = 0; _r < 8; _r++) {                                        \
            const int _j    = tid + _r * 128;                                   \
            const int _tile = _j >> 9;                                          \
            const int _rem  = _j & 511;                                         \
            const int _row  = _rem >> 3;                                        \
            const int _g    = _rem & 7;                                         \
            const size_t _go = (size_t)(bT0 + _kv0 + _row) * QKV_N              \
                               + C_ * (1 + _tile) + h * 64 + _g * 8;            \
            cp_async16(_sb + _tile * AKT_B + (uint32_t)(_row * 144 + _g * 16),  \
                       qh_g + _go);                                             \
        }                                                                       \
        CP_COMMIT();                                                            \
    } while (0)

    ISSUE_KT(0);
    if (nkt > 1) ISSUE_KT(1);

    const int qrow0 = q0 + wid * 16 + (lid >> 2);   // global q row (half 0)
    const int qrow1 = qrow0 + 8;

    for (int kt = 0; kt < nkt; kt++) {
        if (kt < nkt - 1) CP_WAIT1();
        else              CP_WAIT0();
        __syncthreads();
        if (kt + 2 < nkt) ISSUE_KT(kt + 2);

        const uint32_t sb = abase + (kt % 3) * ASTG_B;
        const int kv0 = kt * 64;

        // ---- S = (Qh+Ql) @ Kh^T ----
        float s[8][4];
#pragma unroll
        for (int jn = 0; jn < 8; jn++) {
#pragma unroll
            for (int q = 0; q < 4; q++) s[jn][q] = 0.f;
            const uint32_t aK = sb +
                (uint32_t)(((jn * 8 + (lid & 7)) * 72 + (lid >> 3) * 8) * 2);
            uint32_t khA[4], khB[4];
            ldm_x4(khA, aK);
            ldm_x4(khB, aK + 64);
            mma_f16(s[jn], qfh[0], &khA[0]);
            mma_f16(s[jn], qfh[1], &khA[2]);
            mma_f16(s[jn], qfh[2], &khB[0]);
            mma_f16(s[jn], qfh[3], &khB[2]);
            mma_f16(s[jn], qfl[0], &khA[0]);
            mma_f16(s[jn], qfl[1], &khA[2]);
            mma_f16(s[jn], qfl[2], &khB[0]);
            mma_f16(s[jn], qfl[3], &khB[2]);
        }

        // scale + causal mask (only the diagonal ktile crosses the boundary)
        const bool need_mask = (kt == nkt - 1);
#pragma unroll
        for (int jn = 0; jn < 8; jn++) {
#pragma unroll
            for (int q = 0; q < 4; q++) s[jn][q] *= 0.125f;
            if (need_mask) {
                const int c = kv0 + jn * 8 + (lid & 3) * 2;
                if (c > qrow0)     s[jn][0] = -1e30f;
                if (c + 1 > qrow0) s[jn][1] = -1e30f;
                if (c > qrow1)     s[jn][2] = -1e30f;
                if (c + 1 > qrow1) s[jn][3] = -1e30f;
            }
        }

        // ---- online softmax (rows qrow0, qrow1 per thread) ----
        float mx0 = s[0][0], mx1 = s[0][2];
#pragma unroll
        for (int jn = 0; jn < 8; jn++) {
            mx0 = fmaxf(mx0, fmaxf(s[jn][0], s[jn][1]));
            mx1 = fmaxf(mx1, fmaxf(s[jn][2], s[jn][3]));
        }
        mx0 = fmaxf(mx0, __shfl_xor_sync(0xffffffffu, mx0, 1));
        mx0 = fmaxf(mx0, __shfl_xor_sync(0xffffffffu, mx0, 2));
        mx1 = fmaxf(mx1, __shfl_xor_sync(0xffffffffu, mx1, 1));
        mx1 = fmaxf(mx1, __shfl_xor_sync(0xffffffffu, mx1, 2));
        const float mn0 = fmaxf(m0r, mx0);
        const float mn1 = fmaxf(m1r, mx1);
        const float cr0 = __expf(m0r - mn0);
        const float cr1 = __expf(m1r - mn1);
        float sm0 = 0.f, sm1 = 0.f;
#pragma unroll
        for (int jn = 0; jn < 8; jn++) {
            s[jn][0] = __expf(s[jn][0] - mn0);
            s[jn][1] = __expf(s[jn][1] - mn0);
            s[jn][2] = __expf(s[jn][2] - mn1);
            s[jn][3] = __expf(s[jn][3] - mn1);
            sm0 += s[jn][0] + s[jn][1];
            sm1 += s[jn][2] + s[jn][3];
        }
        sm0 += __shfl_xor_sync(0xffffffffu, sm0, 1);
        sm0 += __shfl_xor_sync(0xffffffffu, sm0, 2);
        sm1 += __shfl_xor_sync(0xffffffffu, sm1, 1);
        sm1 += __shfl_xor_sync(0xffffffffu, sm1, 2);
        l0r = l0r * cr0 + sm0;
        l1r = l1r * cr1 + sm1;
        m0r = mn0; m1r = mn1;
#pragma unroll
        for (int j = 0; j < 8; j++) {
            o[j][0] *= cr0; o[j][1] *= cr0;
            o[j][2] *= cr1; o[j][3] *= cr1;
        }

        // ---- P -> fp16 hi/lo A-fragments ----
        uint32_t ph[4][4], pl[4][4];
#pragma unroll
        for (int t = 0; t < 4; t++) {
            ph[t][0] = pack_f16x2(s[2 * t][1], s[2 * t][0]);
            ph[t][1] = pack_f16x2(s[2 * t][3], s[2 * t][2]);
            ph[t][2] = pack_f16x2(s[2 * t + 1][1], s[2 * t + 1][0]);
            ph[t][3] = pack_f16x2(s[2 * t + 1][3], s[2 * t + 1][2]);
            float2 u0 = unpack_f16x2(ph[t][0]);
            float2 u1 = unpack_f16x2(ph[t][1]);
            float2 u2 = unpack_f16x2(ph[t][2]);
            float2 u3 = unpack_f16x2(ph[t][3]);
            pl[t][0] = pack_f16x2(s[2 * t][1] - u0.y,     s[2 * t][0] - u0.x);
            pl[t][1] = pack_f16x2(s[2 * t][3] - u1.y,     s[2 * t][2] - u1.x);
            pl[t][2] = pack_f16x2(s[2 * t + 1][1] - u2.y, s[2 * t + 1][0] - u2.x);
            pl[t][3] = pack_f16x2(s[2 * t + 1][3] - u3.y, s[2 * t + 1][2] - u3.x);
        }

        // ---- O += (Ph+Pl) @ Vh ----
        const uint32_t vb = sb + AKT_B;
#pragma unroll
        for (int jp = 0; jp < 4; jp++) {
#pragma unroll
            for (int kc = 0; kc < 4; kc++) {
                const uint32_t aV = vb + (uint32_t)((
                    (kc * 16 + ((lid >> 3) & 1) * 8 + (lid & 7)) * 72 +
                    jp * 16 + (lid >> 4) * 8) * 2);
                uint32_t vh[4];
                ldm_x4_t(vh, aV);
                mma_f16(o[2 * jp],     ph[kc], &vh[0]);
                mma_f16(o[2 * jp + 1], ph[kc], &vh[2]);
                mma_f16(o[2 * jp],     pl[kc], &vh[0]);
                mma_f16(o[2 * jp + 1], pl[kc], &vh[2]);
            }
        }
    }
#undef ISSUE_KT

    // ---- epilogue: normalize, split to fp16 hi/lo, write ch/cl ----
    const float inv0 = 1.f / l0r;
    const float inv1 = 1.f / l1r;
    const size_t r0 = (size_t)(bT0 + qrow0) * C_;
    const size_t r1 = (size_t)(bT0 + qrow1) * C_;
#pragma unroll
    for (int jn = 0; jn < 8; jn++) {
        const int col = h * 64 + jn * 8 + (lid & 3) * 2;
        float e0 = o[jn][0] * inv0, e1 = o[jn][1] * inv0;
        float e2 = o[jn][2] * inv1, e3 = o[jn][3] * inv1;
        uint32_t h0 = pack_f16x2(e1, e0);
        uint32_t h1 = pack_f16x2(e3, e2);
        float2 u0 = unpack_f16x2(h0);
        float2 u1 = unpack_f16x2(h1);
        uint32_t l0 = pack_f16x2(e1 - u0.y, e0 - u0.x);
        uint32_t l1 = pack_f16x2(e3 - u1.y, e2 - u1.x);
        *reinterpret_cast<uint32_t*>(&ch_g[r0 + col]) = h0;
        *reinterpret_cast<uint32_t*>(&ch_g[r1 + col]) = h1;
        *reinterpret_cast<uint32_t*>(&cl_g[r0 + col]) = l0;
        *reinterpret_cast<uint32_t*>(&cl_g[r1 + col]) = l1;
    }
}

// ---------------------------------------------------------------------------
// kernel_launch
// ---------------------------------------------------------------------------
extern "C" void kernel_launch(void* const* d_in, const int* in_sizes, int n_in,
                              void* d_out, int out_size)
{
    const float* x      = (const float*)d_in[0];  // [B,T,C]
    const float* w_qkv  = (const float*)d_in[1];  // [3C,C]
    const float* w_proj = (const float*)d_in[2];  // [C,C]
    float* out = (float*)d_out;                   // [B,T,C]

    __half *xh, *xl, *wqh, *wph, *qh, *ql, *ch, *cl;
    cudaGetSymbolAddress((void**)&xh,  g_xh);
    cudaGetSymbolAddress((void**)&xl,  g_xl);
    cudaGetSymbolAddress((void**)&wqh, g_wqh);
    cudaGetSymbolAddress((void**)&wph, g_wph);
    cudaGetSymbolAddress((void**)&qh,  g_qh);
    cudaGetSymbolAddress((void**)&ql,  g_ql);
    cudaGetSymbolAddress((void**)&ch,  g_ch);
    cudaGetSymbolAddress((void**)&cl,  g_cl);

    cudaFuncSetAttribute(gemm_mma_f16x2<true>,
                         cudaFuncAttributeMaxDynamicSharedMemorySize, GEMM_SMEM);
    cudaFuncSetAttribute(gemm_mma_f16x2<false>,
                         cudaFuncAttributeMaxDynamicSharedMemorySize, GEMM_SMEM);
    cudaFuncSetAttribute(attn_mma,
                         cudaFuncAttributeMaxDynamicSharedMemorySize, ATT_SMEM);

    // Splits / converts
    split_f16<<<(M_ * C_ / 4 + 255) / 256, 256>>>(x, xh, xl, M_ * C_ / 4);
    conv_f16<<<(QKV_N * C_ / 4 + 255) / 256, 256>>>(w_qkv, wqh, QKV_N * C_ / 4);
    conv_f16<<<(C_ * C_ / 4 + 255) / 256, 256>>>(w_proj, wph, C_ * C_ / 4);

    // 1) QKV projection -> split fp16 output (qh/ql)
    dim3 g1(QKV_N / 128, M_ / 128);
    gemm_mma_f16x2<true><<<g1, 256, GEMM_SMEM>>>(
        xh, xl, wqh, nullptr, qh, ql, M_, QKV_N, C_);

    // 2) Tensor-core causal flash attention -> split fp16 ctx (ch/cl)
    dim3 g2(T_ / 64, B_ * H_);
    attn_mma<<<g2, 128, ATT_SMEM>>>(qh, ql, ch, cl);

    // 3) Output projection -> fp32 out
    dim3 g3(C_ / 128, M_ / 128);
    gemm_mma_f16x2<false><<<g3, 256, GEMM_SMEM>>>(
        ch, cl, wph, out, nullptr, nullptr, M_, C_, C_);
}

// round 10
// speedup vs baseline: 1.2263x; 1.0456x over previous
#include <cuda_runtime.h>
#include <cuda_fp16.h>
#include <cstdint>

// Problem constants
#define B_  4
#define T_  2048
#define C_  1024
#define H_  16
#define D_  64
#define M_  (B_ * T_)       // 8192 rows
#define QKV_N (3 * C_)      // 3072

// ---------------------------------------------------------------------------
// Scratch (device globals; no runtime allocation allowed)
// ---------------------------------------------------------------------------
__device__ __half g_xh[(size_t)M_ * C_],    g_xl[(size_t)M_ * C_];
__device__ __half g_wqh[(size_t)QKV_N * C_];
__device__ __half g_wph[(size_t)C_ * C_];
__device__ __half g_qh[(size_t)M_ * QKV_N], g_ql[(size_t)M_ * QKV_N];
__device__ __half g_ch[(size_t)M_ * C_],    g_cl[(size_t)M_ * C_];

// ---------------------------------------------------------------------------
// PTX helpers (all non-arch-gated sm_80/sm_90 instructions)
// ---------------------------------------------------------------------------
__device__ __forceinline__ uint32_t smem_u32(const void* p) {
    uint32_t a;
    asm("{ .reg .u64 t; cvta.to.shared.u64 t, %1; cvt.u32.u64 %0, t; }"
        : "=r"(a) : "l"(p));
    return a;
}
__device__ __forceinline__ void cp_async16(uint32_t s, const void* g) {
    asm volatile("cp.async.cg.shared.global [%0], [%1], 16;"
                 :: "r"(s), "l"(g) : "memory");
}
#define CP_COMMIT() asm volatile("cp.async.commit_group;" ::: "memory")
#define CP_WAIT0()  asm volatile("cp.async.wait_group 0;" ::: "memory")
#define CP_WAIT1()  asm volatile("cp.async.wait_group 1;" ::: "memory")

__device__ __forceinline__ void ldm_x4(uint32_t* r, uint32_t a) {
    asm volatile("ldmatrix.sync.aligned.m8n8.x4.shared.b16 {%0,%1,%2,%3}, [%4];"
        : "=r"(r[0]), "=r"(r[1]), "=r"(r[2]), "=r"(r[3]) : "r"(a));
}
__device__ __forceinline__ void ldm_x4_t(uint32_t* r, uint32_t a) {
    asm volatile("ldmatrix.sync.aligned.m8n8.x4.trans.shared.b16 {%0,%1,%2,%3}, [%4];"
        : "=r"(r[0]), "=r"(r[1]), "=r"(r[2]), "=r"(r[3]) : "r"(a));
}
__device__ __forceinline__ void mma_f16(float* d, const uint32_t* a, const uint32_t* b) {
    asm volatile(
        "mma.sync.aligned.m16n8k16.row.col.f32.f16.f16.f32 "
        "{%0,%1,%2,%3}, {%4,%5,%6,%7}, {%8,%9}, {%0,%1,%2,%3};"
        : "+f"(d[0]), "+f"(d[1]), "+f"(d[2]), "+f"(d[3])
        : "r"(a[0]), "r"(a[1]), "r"(a[2]), "r"(a[3]), "r"(b[0]), "r"(b[1]));
}
// pack two f32 -> f16x2 ({hi -> upper16, lo -> lower16})
__device__ __forceinline__ uint32_t pack_f16x2(float hi, float lo) {
    uint32_t d;
    asm("cvt.rn.f16x2.f32 %0, %1, %2;" : "=r"(d) : "f"(hi), "f"(lo));
    return d;
}
// unpack f16x2 -> float2 (.x = lower half, .y = upper half)
__device__ __forceinline__ float2 unpack_f16x2(uint32_t p) {
    __half2 h = *reinterpret_cast<__half2*>(&p);
    return __half22float2(h);
}

// ---------------------------------------------------------------------------
// Split fp32 -> (hi, lo) fp16   |   Convert fp32 -> fp16 (hi only, weights)
// ---------------------------------------------------------------------------
__global__ __launch_bounds__(256) void split_f16(
    const float* __restrict__ in, __half* __restrict__ hi,
    __half* __restrict__ lo, int n4)
{
    int i = blockIdx.x * blockDim.x + threadIdx.x;
    if (i >= n4) return;
    float4 v = reinterpret_cast<const float4*>(in)[i];
    uint32_t h0 = pack_f16x2(v.y, v.x);
    uint32_t h1 = pack_f16x2(v.w, v.z);
    float2 u0 = unpack_f16x2(h0);
    float2 u1 = unpack_f16x2(h1);
    uint32_t l0 = pack_f16x2(v.y - u0.y, v.x - u0.x);
    uint32_t l1 = pack_f16x2(v.w - u1.y, v.z - u1.x);
    reinterpret_cast<uint2*>(hi)[i] = make_uint2(h0, h1);
    reinterpret_cast<uint2*>(lo)[i] = make_uint2(l0, l1);
}

__global__ __launch_bounds__(256) void conv_f16(
    const float* __restrict__ in, __half* __restrict__ hi, int n4)
{
    int i = blockIdx.x * blockDim.x + threadIdx.x;
    if (i >= n4) return;
    float4 v = reinterpret_cast<const float4*>(in)[i];
    reinterpret_cast<uint2*>(hi)[i] =
        make_uint2(pack_f16x2(v.y, v.x), pack_f16x2(v.w, v.z));
}

// ---------------------------------------------------------------------------
// mma.sync fp16x2 GEMM: C[M,N] = (Ah+Al)[M,K] @ Bh[N,K]^T.
// 128x128 CTA tile, BK=64, 8 warps (2x4), warp tile 64x32.
// B fragments via paired ldm_x4 with mma-operand-ordered lane mapping.
// 2-stage cp.async pipeline; 2 CTAs/SM. Stage = Ah | Al | Bh (72-b16 rows).
// SPLIT=true: write fp16 hi/lo instead of fp32.
// ---------------------------------------------------------------------------
#define TILE_B  18432                   // 128 rows * 72 b16 * 2B
#define STAGE_B (3 * TILE_B)            // 55296
#define GEMM_SMEM (2 * STAGE_B)         // 110592 (x2 CTAs = 216KB <= 228KB)

template <bool SPLIT>
__global__ __launch_bounds__(256, 2) void gemm_mma_f16x2(
    const __half* __restrict__ Ah, const __half* __restrict__ Al,
    const __half* __restrict__ Bh,
    float* __restrict__ Cf, __half* __restrict__ Ch,
    __half* __restrict__ Cl, int M, int N, int K)
{
    extern __shared__ char smc[];
    const uint32_t sbase = smem_u32(smc);
    const int tid = threadIdx.x;
    const int lid = tid & 31;
    const int wid = tid >> 5;
    const int wm  = wid >> 2;      // 0..1
    const int wn  = wid & 3;       // 0..3
    const int m0  = blockIdx.y * 128;
    const int n0  = blockIdx.x * 128;

    float acc[4][4][4];
#pragma unroll
    for (int i = 0; i < 4; i++)
#pragma unroll
        for (int j = 0; j < 4; j++)
#pragma unroll
            for (int q = 0; q < 4; q++) acc[i][j][q] = 0.f;

    // ldmatrix per-thread base offsets (b16 units within a tile, stride 72)
    const int a_base = (wm * 64 + (lid & 15)) * 72 + ((lid >> 4) * 8);
    // B paired-x4 mapping: matrices [n0k0, n0k1, n1k0, n1k1]
    const int b_base = (wn * 32 + (lid & 7) + ((lid >> 4) * 8)) * 72 +
                       (((lid >> 3) & 1) * 8);
    const int NS = K / 64;

#define ISSUE_STAGE(S)                                                          \
    do {                                                                        \
        const int _kc = (S) * 64;                                               \
        const uint32_t _sb = sbase + ((S) & 1) * STAGE_B;                       \
        _Pragma("unroll")                                                       \
        for (int _r = 0; _r < 4; _r++) {                                        \
            const int _c   = tid + _r * 256;      /* 0..1023 */                 \
            const int _row = _c >> 3;             /* 0..127  */                 \
            const int _c8  = (_c & 7) * 8;        /* 0..56   */                 \
            const uint32_t _so = _sb + (uint32_t)((_row * 72 + _c8) * 2);       \
            const size_t _ga = (size_t)(m0 + _row) * K + _kc + _c8;             \
            const size_t _gb = (size_t)(n0 + _row) * K + _kc + _c8;             \
            cp_async16(_so,              Ah + _ga);                             \
            cp_async16(_so + TILE_B,     Al + _ga);                             \
            cp_async16(_so + 2 * TILE_B, Bh + _gb);                             \
        }                                                                       \
        CP_COMMIT();                                                            \
    } while (0)

    ISSUE_STAGE(0);

    for (int s = 0; s < NS; s++) {
        CP_WAIT0();
        __syncthreads();
        if (s + 1 < NS) ISSUE_STAGE(s + 1);

        const uint32_t sb = sbase + (s & 1) * STAGE_B;
#pragma unroll
        for (int ks = 0; ks < 4; ks++) {
            uint32_t ah[4][4], al[4][4], b01[4], b23[4];
#pragma unroll
            for (int mi = 0; mi < 4; mi++) {
                const uint32_t ao = sb +
                    (uint32_t)((a_base + mi * 16 * 72 + ks * 16) * 2);
                ldm_x4(ah[mi], ao);
                ldm_x4(al[mi], ao + TILE_B);
            }
            {
                const uint32_t bo = sb + 2 * TILE_B +
                    (uint32_t)((b_base + ks * 16) * 2);
                ldm_x4(b01, bo);                       // n-chunks 0,1
                ldm_x4(b23, bo + 16 * 72 * 2);         // n-chunks 2,3
            }
            // 2 passes: same accumulator revisited at distance 16
#pragma unroll
            for (int mi = 0; mi < 4; mi++) {
                mma_f16(acc[mi][0], ah[mi], &b01[0]);
                mma_f16(acc[mi][1], ah[mi], &b01[2]);
                mma_f16(acc[mi][2], ah[mi], &b23[0]);
                mma_f16(acc[mi][3], ah[mi], &b23[2]);
            }
#pragma unroll
            for (int mi = 0; mi < 4; mi++) {
                mma_f16(acc[mi][0], al[mi], &b01[0]);
                mma_f16(acc[mi][1], al[mi], &b01[2]);
                mma_f16(acc[mi][2], al[mi], &b23[0]);
                mma_f16(acc[mi][3], al[mi], &b23[2]);
            }
        }
    }
#undef ISSUE_STAGE

#pragma unroll
    for (int mi = 0; mi < 4; mi++)
#pragma unroll
        for (int ni = 0; ni < 4; ni++) {
            const int row = m0 + wm * 64 + mi * 16 + (lid >> 2);
            const int col = n0 + wn * 32 + ni * 8 + (lid & 3) * 2;
            if (SPLIT) {
                uint32_t h0 = pack_f16x2(acc[mi][ni][1], acc[mi][ni][0]);
                uint32_t h1 = pack_f16x2(acc[mi][ni][3], acc[mi][ni][2]);
                float2 u0 = unpack_f16x2(h0);
                float2 u1 = unpack_f16x2(h1);
                uint32_t l0 = pack_f16x2(acc[mi][ni][1] - u0.y,
                                         acc[mi][ni][0] - u0.x);
                uint32_t l1 = pack_f16x2(acc[mi][ni][3] - u1.y,
                                         acc[mi][ni][2] - u1.x);
                *reinterpret_cast<uint32_t*>(&Ch[(size_t)row * N + col])       = h0;
                *reinterpret_cast<uint32_t*>(&Ch[(size_t)(row + 8) * N + col]) = h1;
                *reinterpret_cast<uint32_t*>(&Cl[(size_t)row * N + col])       = l0;
                *reinterpret_cast<uint32_t*>(&Cl[(size_t)(row + 8) * N + col]) = l1;
            } else {
                float2 v0 = make_float2(acc[mi][ni][0], acc[mi][ni][1]);
                float2 v1 = make_float2(acc[mi][ni][2], acc[mi][ni][3]);
                *reinterpret_cast<float2*>(&Cf[(size_t)row * N + col])       = v0;
                *reinterpret_cast<float2*>(&Cf[(size_t)(row + 8) * N + col]) = v1;
            }
        }
}

// ---------------------------------------------------------------------------
// Tensor-core causal flash attention, fp16x2 split precision.
// CTA: 128 thr (4 warps), 64-row Q tile per CTA -> 4 CTAs/SM.
// K/V 64-row hi-only tiles, 3-stage cp.async pipeline.
// Warp w owns Q rows [16w,16w+16). Q split hi/lo; K,V rounded to fp16.
// ---------------------------------------------------------------------------
#define AKT_B   9216                 // 64 rows * 72 b16 * 2B
#define ASTG_B  (2 * AKT_B)          // Kh | Vh
#define ATT_SMEM (3 * ASTG_B)        // 55296 (x4 CTAs = 216KB <= 228KB)

__global__ __launch_bounds__(128, 4) void attn_mma(
    const __half* __restrict__ qh_g, const __half* __restrict__ ql_g,
    __half* __restrict__ ch_g, __half* __restrict__ cl_g)
{
    extern __shared__ char smc[];
    const uint32_t abase = smem_u32(smc);
    const int tid = threadIdx.x;
    const int lid = tid & 31;
    const int wid = tid >> 5;
    const int qi  = (int)gridDim.x - 1 - (int)blockIdx.x;  // long CTAs first
    const int bh  = blockIdx.y;
    const int b   = bh >> 4;
    const int h   = bh & 15;
    const int q0  = qi * 64;
    const int bT0 = b * T_;
    const int nkt = qi + 1;

    // ---- Q fragments (hi/lo), loaded once from global ----
    uint32_t qfh[4][4], qfl[4][4];
    {
        const int r0 = bT0 + q0 + wid * 16 + (lid >> 2);
#pragma unroll
        for (int kc = 0; kc < 4; kc++) {
            const int c0 = h * 64 + kc * 16 + (lid & 3) * 2;
            const size_t o00 = (size_t)r0 * QKV_N + c0;
            const size_t o10 = o00 + 8 * QKV_N;
            qfh[kc][0] = *reinterpret_cast<const uint32_t*>(qh_g + o00);
            qfh[kc][1] = *reinterpret_cast<const uint32_t*>(qh_g + o10);
            qfh[kc][2] = *reinterpret_cast<const uint32_t*>(qh_g + o00 + 8);
            qfh[kc][3] = *reinterpret_cast<const uint32_t*>(qh_g + o10 + 8);
            qfl[kc][0] = *reinterpret_cast<const uint32_t*>(ql_g + o00);
            qfl[kc][1] = *reinterpret_cast<const uint32_t*>(ql_g + o10);
            qfl[kc][2] = *reinterpret_cast<const uint32_t*>(ql_g + o00 + 8);
            qfl[kc][3] = *reinterpret_cast<const uint32_t*>(ql_g + o10 + 8);
        }
    }

    float o[8][4];
#pragma unroll
    for (int j = 0; j < 8; j++)
#pragma unroll
        for (int q = 0; q < 4; q++) o[j][q] = 0.f;
    float m0r = -1e30f, m1r = -1e30f, l0r = 0.f, l1r = 0.f;

    // K/V hi-only tile loader: 2 tiles x 64 rows x 8 groups = 1024 jobs / 128 thr
#define ISSUE_KT(KT)                                                            \
    do {                                                                        \
        const uint32_t _sb = abase + ((KT) % 3) * ASTG_B;                       \
        const int _kv0 = (KT) * 64;                                             \
        _Pragma("unroll")                                                       \
        for (int _r = 0; _r < 8; _r++) {                                        \
            const int _j    = tid + _r * 128;                                   \
            const int _tile = _j >> 9;                                          \
            const int _rem  = _j & 511;                                         \
            const int _row  = _rem >> 3;                                        \
            const int _g    = _rem & 7;                                         \
            const size_t _go = (size_t)(bT0 + _kv0 + _row) * QKV_N              \
                               + C_ * (1 + _tile) + h * 64 + _g * 8;            \
            cp_async16(_sb + _tile * AKT_B + (uint32_t)(_row * 144 + _g * 16),  \
                       qh_g + _go);                                             \
        }                                                                       \
        CP_COMMIT();                                                            \
    } while (0)

    ISSUE_KT(0);
    if (nkt > 1) ISSUE_KT(1);

    const int qrow0 = q0 + wid * 16 + (lid >> 2);   // global q row (half 0)
    const int qrow1 = qrow0 + 8;

    for (int kt = 0; kt < nkt; kt++) {
        if (kt < nkt - 1) CP_WAIT1();
        else              CP_WAIT0();
        __syncthreads();
        if (kt + 2 < nkt) ISSUE_KT(kt + 2);

        const uint32_t sb = abase + (kt % 3) * ASTG_B;
        const int kv0 = kt * 64;

        // ---- S = (Qh+Ql) @ Kh^T ----
        float s[8][4];
#pragma unroll
        for (int jn = 0; jn < 8; jn++) {
#pragma unroll
            for (int q = 0; q < 4; q++) s[jn][q] = 0.f;
            const uint32_t aK = sb +
                (uint32_t)(((jn * 8 + (lid & 7)) * 72 + (lid >> 3) * 8) * 2);
            uint32_t khA[4], khB[4];
            ldm_x4(khA, aK);
            ldm_x4(khB, aK + 64);
            mma_f16(s[jn], qfh[0], &khA[0]);
            mma_f16(s[jn], qfh[1], &khA[2]);
            mma_f16(s[jn], qfh[2], &khB[0]);
            mma_f16(s[jn], qfh[3], &khB[2]);
            mma_f16(s[jn], qfl[0], &khA[0]);
            mma_f16(s[jn], qfl[1], &khA[2]);
            mma_f16(s[jn], qfl[2], &khB[0]);
            mma_f16(s[jn], qfl[3], &khB[2]);
        }

        // scale + causal mask (only the diagonal ktile crosses the boundary)
        const bool need_mask = (kt == nkt - 1);
#pragma unroll
        for (int jn = 0; jn < 8; jn++) {
#pragma unroll
            for (int q = 0; q < 4; q++) s[jn][q] *= 0.125f;
            if (need_mask) {
                const int c = kv0 + jn * 8 + (lid & 3) * 2;
                if (c > qrow0)     s[jn][0] = -1e30f;
                if (c + 1 > qrow0) s[jn][1] = -1e30f;
                if (c > qrow1)     s[jn][2] = -1e30f;
                if (c + 1 > qrow1) s[jn][3] = -1e30f;
            }
        }

        // ---- online softmax (rows qrow0, qrow1 per thread) ----
        float mx0 = s[0][0], mx1 = s[0][2];
#pragma unroll
        for (int jn = 0; jn < 8; jn++) {
            mx0 = fmaxf(mx0, fmaxf(s[jn][0], s[jn][1]));
            mx1 = fmaxf(mx1, fmaxf(s[jn][2], s[jn][3]));
        }
        mx0 = fmaxf(mx0, __shfl_xor_sync(0xffffffffu, mx0, 1));
        mx0 = fmaxf(mx0, __shfl_xor_sync(0xffffffffu, mx0, 2));
        mx1 = fmaxf(mx1, __shfl_xor_sync(0xffffffffu, mx1, 1));
        mx1 = fmaxf(mx1, __shfl_xor_sync(0xffffffffu, mx1, 2));
        const float mn0 = fmaxf(m0r, mx0);
        const float mn1 = fmaxf(m1r, mx1);
        const float cr0 = __expf(m0r - mn0);
        const float cr1 = __expf(m1r - mn1);
        float sm0 = 0.f, sm1 = 0.f;
#pragma unroll
        for (int jn = 0; jn < 8; jn++) {
            s[jn][0] = __expf(s[jn][0] - mn0);
            s[jn][1] = __expf(s[jn][1] - mn0);
            s[jn][2] = __expf(s[jn][2] - mn1);
            s[jn][3] = __expf(s[jn][3] - mn1);
            sm0 += s[jn][0] + s[jn][1];
            sm1 += s[jn][2] + s[jn][3];
        }
        sm0 += __shfl_xor_sync(0xffffffffu, sm0, 1);
        sm0 += __shfl_xor_sync(0xffffffffu, sm0, 2);
        sm1 += __shfl_xor_sync(0xffffffffu, sm1, 1);
        sm1 += __shfl_xor_sync(0xffffffffu, sm1, 2);
        l0r = l0r * cr0 + sm0;
        l1r = l1r * cr1 + sm1;
        m0r = mn0; m1r = mn1;
#pragma unroll
        for (int j = 0; j < 8; j++) {
            o[j][0] *= cr0; o[j][1] *= cr0;
            o[j][2] *= cr1; o[j][3] *= cr1;
        }

        // ---- P -> fp16 hi/lo A-fragments ----
        uint32_t ph[4][4], pl[4][4];
#pragma unroll
        for (int t = 0; t < 4; t++) {
            ph[t][0] = pack_f16x2(s[2 * t][1], s[2 * t][0]);
            ph[t][1] = pack_f16x2(s[2 * t][3], s[2 * t][2]);
            ph[t][2] = pack_f16x2(s[2 * t + 1][1], s[2 * t + 1][0]);
            ph[t][3] = pack_f16x2(s[2 * t + 1][3], s[2 * t + 1][2]);
            float2 u0 = unpack_f16x2(ph[t][0]);
            float2 u1 = unpack_f16x2(ph[t][1]);
            float2 u2 = unpack_f16x2(ph[t][2]);
            float2 u3 = unpack_f16x2(ph[t][3]);
            pl[t][0] = pack_f16x2(s[2 * t][1] - u0.y,     s[2 * t][0] - u0.x);
            pl[t][1] = pack_f16x2(s[2 * t][3] - u1.y,     s[2 * t][2] - u1.x);
            pl[t][2] = pack_f16x2(s[2 * t + 1][1] - u2.y, s[2 * t + 1][0] - u2.x);
            pl[t][3] = pack_f16x2(s[2 * t + 1][3] - u3.y, s[2 * t + 1][2] - u3.x);
        }

        // ---- O += (Ph+Pl) @ Vh ----
        const uint32_t vb = sb + AKT_B;
#pragma unroll
        for (int jp = 0; jp < 4; jp++) {
#pragma unroll
            for (int kc = 0; kc < 4; kc++) {
                const uint32_t aV = vb + (uint32_t)((
                    (kc * 16 + ((lid >> 3) & 1) * 8 + (lid & 7)) * 72 +
                    jp * 16 + (lid >> 4) * 8) * 2);
                uint32_t vh[4];
                ldm_x4_t(vh, aV);
                mma_f16(o[2 * jp],     ph[kc], &vh[0]);
                mma_f16(o[2 * jp + 1], ph[kc], &vh[2]);
                mma_f16(o[2 * jp],     pl[kc], &vh[0]);
                mma_f16(o[2 * jp + 1], pl[kc], &vh[2]);
            }
        }
    }
#undef ISSUE_KT

    // ---- epilogue: normalize, split to fp16 hi/lo, write ch/cl ----
    const float inv0 = 1.f / l0r;
    const float inv1 = 1.f / l1r;
    const size_t r0 = (size_t)(bT0 + qrow0) * C_;
    const size_t r1 = (size_t)(bT0 + qrow1) * C_;
#pragma unroll
    for (int jn = 0; jn < 8; jn++) {
        const int col = h * 64 + jn * 8 + (lid & 3) * 2;
        float e0 = o[jn][0] * inv0, e1 = o[jn][1] * inv0;
        float e2 = o[jn][2] * inv1, e3 = o[jn][3] * inv1;
        uint32_t h0 = pack_f16x2(e1, e0);
        uint32_t h1 = pack_f16x2(e3, e2);
        float2 u0 = unpack_f16x2(h0);
        float2 u1 = unpack_f16x2(h1);
        uint32_t l0 = pack_f16x2(e1 - u0.y, e0 - u0.x);
        uint32_t l1 = pack_f16x2(e3 - u1.y, e2 - u1.x);
        *reinterpret_cast<uint32_t*>(&ch_g[r0 + col]) = h0;
        *reinterpret_cast<uint32_t*>(&ch_g[r1 + col]) = h1;
        *reinterpret_cast<uint32_t*>(&cl_g[r0 + col]) = l0;
        *reinterpret_cast<uint32_t*>(&cl_g[r1 + col]) = l1;
    }
}

// ---------------------------------------------------------------------------
// kernel_launch
// ---------------------------------------------------------------------------
extern "C" void kernel_launch(void* const* d_in, const int* in_sizes, int n_in,
                              void* d_out, int out_size)
{
    const float* x      = (const float*)d_in[0];  // [B,T,C]
    const float* w_qkv  = (const float*)d_in[1];  // [3C,C]
    const float* w_proj = (const float*)d_in[2];  // [C,C]
    float* out = (float*)d_out;                   // [B,T,C]

    __half *xh, *xl, *wqh, *wph, *qh, *ql, *ch, *cl;
    cudaGetSymbolAddress((void**)&xh,  g_xh);
    cudaGetSymbolAddress((void**)&xl,  g_xl);
    cudaGetSymbolAddress((void**)&wqh, g_wqh);
    cudaGetSymbolAddress((void**)&wph, g_wph);
    cudaGetSymbolAddress((void**)&qh,  g_qh);
    cudaGetSymbolAddress((void**)&ql,  g_ql);
    cudaGetSymbolAddress((void**)&ch,  g_ch);
    cudaGetSymbolAddress((void**)&cl,  g_cl);

    cudaFuncSetAttribute(gemm_mma_f16x2<true>,
                         cudaFuncAttributeMaxDynamicSharedMemorySize, GEMM_SMEM);
    cudaFuncSetAttribute(gemm_mma_f16x2<false>,
                         cudaFuncAttributeMaxDynamicSharedMemorySize, GEMM_SMEM);
    cudaFuncSetAttribute(attn_mma,
                         cudaFuncAttributeMaxDynamicSharedMemorySize, ATT_SMEM);

    // Splits / converts
    split_f16<<<(M_ * C_ / 4 + 255) / 256, 256>>>(x, xh, xl, M_ * C_ / 4);
    conv_f16<<<(QKV_N * C_ / 4 + 255) / 256, 256>>>(w_qkv, wqh, QKV_N * C_ / 4);
    conv_f16<<<(C_ * C_ / 4 + 255) / 256, 256>>>(w_proj, wph, C_ * C_ / 4);

    // 1) QKV projection -> split fp16 output (qh/ql)
    dim3 g1(QKV_N / 128, M_ / 128);
    gemm_mma_f16x2<true><<<g1, 256, GEMM_SMEM>>>(
        xh, xl, wqh, nullptr, qh, ql, M_, QKV_N, C_);

    // 2) Tensor-core causal flash attention -> split fp16 ctx (ch/cl)
    dim3 g2(T_ / 64, B_ * H_);
    attn_mma<<<g2, 128, ATT_SMEM>>>(qh, ql, ch, cl);

    // 3) Output projection -> fp32 out
    dim3 g3(C_ / 128, M_ / 128);
    gemm_mma_f16x2<false><<<g3, 256, GEMM_SMEM>>>(
        ch, cl, wph, out, nullptr, nullptr, M_, C_, C_);
}

// round 11
// speedup vs baseline: 1.2925x; 1.0540x over previous
#include <cuda_runtime.h>
#include <cuda_fp16.h>
#include <cstdint>

// Problem constants
#define B_  4
#define T_  2048
#define C_  1024
#define H_  16
#define D_  64
#define M_  (B_ * T_)       // 8192 rows
#define QKV_N (3 * C_)      // 3072

// ---------------------------------------------------------------------------
// Scratch (device globals; no runtime allocation allowed)
// ---------------------------------------------------------------------------
__device__ __half g_xh[(size_t)M_ * C_],    g_xl[(size_t)M_ * C_];
__device__ __half g_wqh[(size_t)QKV_N * C_];
__device__ __half g_wph[(size_t)C_ * C_];
__device__ __half g_qh[(size_t)M_ * QKV_N], g_ql[(size_t)M_ * QKV_N];
__device__ __half g_ch[(size_t)M_ * C_],    g_cl[(size_t)M_ * C_];

// ---------------------------------------------------------------------------
// PTX helpers (all non-arch-gated sm_80/sm_90 instructions)
// ---------------------------------------------------------------------------
__device__ __forceinline__ uint32_t smem_u32(const void* p) {
    uint32_t a;
    asm("{ .reg .u64 t; cvta.to.shared.u64 t, %1; cvt.u32.u64 %0, t; }"
        : "=r"(a) : "l"(p));
    return a;
}
__device__ __forceinline__ void cp_async16(uint32_t s, const void* g) {
    asm volatile("cp.async.cg.shared.global [%0], [%1], 16;"
                 :: "r"(s), "l"(g) : "memory");
}
#define CP_COMMIT() asm volatile("cp.async.commit_group;" ::: "memory")
#define CP_WAIT0()  asm volatile("cp.async.wait_group 0;" ::: "memory")
#define CP_WAIT1()  asm volatile("cp.async.wait_group 1;" ::: "memory")

__device__ __forceinline__ void ldm_x4(uint32_t* r, uint32_t a) {
    asm volatile("ldmatrix.sync.aligned.m8n8.x4.shared.b16 {%0,%1,%2,%3}, [%4];"
        : "=r"(r[0]), "=r"(r[1]), "=r"(r[2]), "=r"(r[3]) : "r"(a));
}
__device__ __forceinline__ void ldm_x4_t(uint32_t* r, uint32_t a) {
    asm volatile("ldmatrix.sync.aligned.m8n8.x4.trans.shared.b16 {%0,%1,%2,%3}, [%4];"
        : "=r"(r[0]), "=r"(r[1]), "=r"(r[2]), "=r"(r[3]) : "r"(a));
}
__device__ __forceinline__ void mma_f16(float* d, const uint32_t* a, const uint32_t* b) {
    asm volatile(
        "mma.sync.aligned.m16n8k16.row.col.f32.f16.f16.f32 "
        "{%0,%1,%2,%3}, {%4,%5,%6,%7}, {%8,%9}, {%0,%1,%2,%3};"
        : "+f"(d[0]), "+f"(d[1]), "+f"(d[2]), "+f"(d[3])
        : "r"(a[0]), "r"(a[1]), "r"(a[2]), "r"(a[3]), "r"(b[0]), "r"(b[1]));
}
// pack two f32 -> f16x2 ({hi -> upper16, lo -> lower16})
__device__ __forceinline__ uint32_t pack_f16x2(float hi, float lo) {
    uint32_t d;
    asm("cvt.rn.f16x2.f32 %0, %1, %2;" : "=r"(d) : "f"(hi), "f"(lo));
    return d;
}
// unpack f16x2 -> float2 (.x = lower half, .y = upper half)
__device__ __forceinline__ float2 unpack_f16x2(uint32_t p) {
    __half2 h = *reinterpret_cast<__half2*>(&p);
    return __half22float2(h);
}

// ---------------------------------------------------------------------------
// Fused prep: x split (hi/lo) + w_qkv conv + w_proj conv in ONE launch.
// Flat float4 job index: [0, NX) x-split, [NX, NX+NWQ) wqkv, rest wproj.
// ---------------------------------------------------------------------------
#define NX_JOBS  (M_ * C_ / 4)
#define NWQ_JOBS (QKV_N * C_ / 4)
#define NWP_JOBS (C_ * C_ / 4)
#define PREP_JOBS (NX_JOBS + NWQ_JOBS + NWP_JOBS)

__global__ __launch_bounds__(256) void prep_f16(
    const float* __restrict__ x, const float* __restrict__ wq,
    const float* __restrict__ wp,
    __half* __restrict__ xh, __half* __restrict__ xl,
    __half* __restrict__ wqh, __half* __restrict__ wph)
{
    int i = blockIdx.x * blockDim.x + threadIdx.x;
    if (i >= PREP_JOBS) return;
    if (i < NX_JOBS) {
        float4 v = reinterpret_cast<const float4*>(x)[i];
        uint32_t h0 = pack_f16x2(v.y, v.x);
        uint32_t h1 = pack_f16x2(v.w, v.z);
        float2 u0 = unpack_f16x2(h0);
        float2 u1 = unpack_f16x2(h1);
        uint32_t l0 = pack_f16x2(v.y - u0.y, v.x - u0.x);
        uint32_t l1 = pack_f16x2(v.w - u1.y, v.z - u1.x);
        reinterpret_cast<uint2*>(xh)[i] = make_uint2(h0, h1);
        reinterpret_cast<uint2*>(xl)[i] = make_uint2(l0, l1);
    } else if (i < NX_JOBS + NWQ_JOBS) {
        int j = i - NX_JOBS;
        float4 v = reinterpret_cast<const float4*>(wq)[j];
        reinterpret_cast<uint2*>(wqh)[j] =
            make_uint2(pack_f16x2(v.y, v.x), pack_f16x2(v.w, v.z));
    } else {
        int j = i - NX_JOBS - NWQ_JOBS;
        float4 v = reinterpret_cast<const float4*>(wp)[j];
        reinterpret_cast<uint2*>(wph)[j] =
            make_uint2(pack_f16x2(v.y, v.x), pack_f16x2(v.w, v.z));
    }
}

// ---------------------------------------------------------------------------
// mma.sync fp16x2 GEMM: C[M,N] = (Ah+Al)[M,K] @ Bh[N,K]^T.
// 128x128 CTA tile, BK=64, 8 warps (2x4), warp tile 64x32.
// 2-stage cp.async pipeline; 2 CTAs/SM. Stage = Ah | Al | Bh (72-b16 rows).
// SPLIT=true: write fp16 hi/lo; lo is skipped for n0 >= C_ (K/V columns,
// whose lo is never consumed downstream).
// ---------------------------------------------------------------------------
#define TILE_B  18432                   // 128 rows * 72 b16 * 2B
#define STAGE_B (3 * TILE_B)            // 55296
#define GEMM_SMEM (2 * STAGE_B)         // 110592 (x2 CTAs = 216KB <= 228KB)

template <bool SPLIT>
__global__ __launch_bounds__(256, 2) void gemm_mma_f16x2(
    const __half* __restrict__ Ah, const __half* __restrict__ Al,
    const __half* __restrict__ Bh,
    float* __restrict__ Cf, __half* __restrict__ Ch,
    __half* __restrict__ Cl, int M, int N, int K)
{
    extern __shared__ char smc[];
    const uint32_t sbase = smem_u32(smc);
    const int tid = threadIdx.x;
    const int lid = tid & 31;
    const int wid = tid >> 5;
    const int wm  = wid >> 2;      // 0..1
    const int wn  = wid & 3;       // 0..3
    const int m0  = blockIdx.y * 128;
    const int n0  = blockIdx.x * 128;

    float acc[4][4][4];
#pragma unroll
    for (int i = 0; i < 4; i++)
#pragma unroll
        for (int j = 0; j < 4; j++)
#pragma unroll
            for (int q = 0; q < 4; q++) acc[i][j][q] = 0.f;

    // ldmatrix per-thread base offsets (b16 units within a tile, stride 72)
    const int a_base = (wm * 64 + (lid & 15)) * 72 + ((lid >> 4) * 8);
    // B paired-x4 mapping: matrices [n0k0, n0k1, n1k0, n1k1]
    const int b_base = (wn * 32 + (lid & 7) + ((lid >> 4) * 8)) * 72 +
                       (((lid >> 3) & 1) * 8);
    const int NS = K / 64;

#define ISSUE_STAGE(S)                                                          \
    do {                                                                        \
        const int _kc = (S) * 64;                                               \
        const uint32_t _sb = sbase + ((S) & 1) * STAGE_B;                       \
        _Pragma("unroll")                                                       \
        for (int _r = 0; _r < 4; _r++) {                                        \
            const int _c   = tid + _r * 256;      /* 0..1023 */                 \
            const int _row = _c >> 3;             /* 0..127  */                 \
            const int _c8  = (_c & 7) * 8;        /* 0..56   */                 \
            const uint32_t _so = _sb + (uint32_t)((_row * 72 + _c8) * 2);       \
            const size_t _ga = (size_t)(m0 + _row) * K + _kc + _c8;             \
            const size_t _gb = (size_t)(n0 + _row) * K + _kc + _c8;             \
            cp_async16(_so,              Ah + _ga);                             \
            cp_async16(_so + TILE_B,     Al + _ga);                             \
            cp_async16(_so + 2 * TILE_B, Bh + _gb);                             \
        }                                                                       \
        CP_COMMIT();                                                            \
    } while (0)

    ISSUE_STAGE(0);

    for (int s = 0; s < NS; s++) {
        CP_WAIT0();
        __syncthreads();
        if (s + 1 < NS) ISSUE_STAGE(s + 1);

        const uint32_t sb = sbase + (s & 1) * STAGE_B;
#pragma unroll
        for (int ks = 0; ks < 4; ks++) {
            uint32_t ah[4][4], al[4][4], b01[4], b23[4];
#pragma unroll
            for (int mi = 0; mi < 4; mi++) {
                const uint32_t ao = sb +
                    (uint32_t)((a_base + mi * 16 * 72 + ks * 16) * 2);
                ldm_x4(ah[mi], ao);
                ldm_x4(al[mi], ao + TILE_B);
            }
            {
                const uint32_t bo = sb + 2 * TILE_B +
                    (uint32_t)((b_base + ks * 16) * 2);
                ldm_x4(b01, bo);                       // n-chunks 0,1
                ldm_x4(b23, bo + 16 * 72 * 2);         // n-chunks 2,3
            }
            // 2 passes: same accumulator revisited at distance 16
#pragma unroll
            for (int mi = 0; mi < 4; mi++) {
                mma_f16(acc[mi][0], ah[mi], &b01[0]);
                mma_f16(acc[mi][1], ah[mi], &b01[2]);
                mma_f16(acc[mi][2], ah[mi], &b23[0]);
                mma_f16(acc[mi][3], ah[mi], &b23[2]);
            }
#pragma unroll
            for (int mi = 0; mi < 4; mi++) {
                mma_f16(acc[mi][0], al[mi], &b01[0]);
                mma_f16(acc[mi][1], al[mi], &b01[2]);
                mma_f16(acc[mi][2], al[mi], &b23[0]);
                mma_f16(acc[mi][3], al[mi], &b23[2]);
            }
        }
    }
#undef ISSUE_STAGE

    const bool want_lo = SPLIT && (n0 < C_);   // lo of K/V cols is never read
#pragma unroll
    for (int mi = 0; mi < 4; mi++)
#pragma unroll
        for (int ni = 0; ni < 4; ni++) {
            const int row = m0 + wm * 64 + mi * 16 + (lid >> 2);
            const int col = n0 + wn * 32 + ni * 8 + (lid & 3) * 2;
            if (SPLIT) {
                uint32_t h0 = pack_f16x2(acc[mi][ni][1], acc[mi][ni][0]);
                uint32_t h1 = pack_f16x2(acc[mi][ni][3], acc[mi][ni][2]);
                *reinterpret_cast<uint32_t*>(&Ch[(size_t)row * N + col])       = h0;
                *reinterpret_cast<uint32_t*>(&Ch[(size_t)(row + 8) * N + col]) = h1;
                if (want_lo) {
                    float2 u0 = unpack_f16x2(h0);
                    float2 u1 = unpack_f16x2(h1);
                    uint32_t l0 = pack_f16x2(acc[mi][ni][1] - u0.y,
                                             acc[mi][ni][0] - u0.x);
                    uint32_t l1 = pack_f16x2(acc[mi][ni][3] - u1.y,
                                             acc[mi][ni][2] - u1.x);
                    *reinterpret_cast<uint32_t*>(&Cl[(size_t)row * N + col])       = l0;
                    *reinterpret_cast<uint32_t*>(&Cl[(size_t)(row + 8) * N + col]) = l1;
                }
            } else {
                float2 v0 = make_float2(acc[mi][ni][0], acc[mi][ni][1]);
                float2 v1 = make_float2(acc[mi][ni][2], acc[mi][ni][3]);
                *reinterpret_cast<float2*>(&Cf[(size_t)row * N + col])       = v0;
                *reinterpret_cast<float2*>(&Cf[(size_t)(row + 8) * N + col]) = v1;
            }
        }
}

// ---------------------------------------------------------------------------
// Tensor-core causal flash attention, fp16x2 split precision.
// CTA: 128 thr (4 warps), 64-row Q tile per CTA -> 4 CTAs/SM.
// K/V 64-row hi-only tiles, 3-stage cp.async pipeline.
// Softmax in log2 domain: scale = 0.125*log2(e), exp2f (single MUFU per exp).
// ---------------------------------------------------------------------------
#define AKT_B   9216                 // 64 rows * 72 b16 * 2B
#define ASTG_B  (2 * AKT_B)          // Kh | Vh
#define ATT_SMEM (3 * ASTG_B)        // 55296 (x4 CTAs = 216KB <= 228KB)
#define SCALE_L2E 0.1803368801111204f   // 0.125 * log2(e)

__global__ __launch_bounds__(128, 4) void attn_mma(
    const __half* __restrict__ qh_g, const __half* __restrict__ ql_g,
    __half* __restrict__ ch_g, __half* __restrict__ cl_g)
{
    extern __shared__ char smc[];
    const uint32_t abase = smem_u32(smc);
    const int tid = threadIdx.x;
    const int lid = tid & 31;
    const int wid = tid >> 5;
    const int qi  = (int)gridDim.x - 1 - (int)blockIdx.x;  // long CTAs first
    const int bh  = blockIdx.y;
    const int b   = bh >> 4;
    const int h   = bh & 15;
    const int q0  = qi * 64;
    const int bT0 = b * T_;
    const int nkt = qi + 1;

    // ---- Q fragments (hi/lo), loaded once from global ----
    uint32_t qfh[4][4], qfl[4][4];
    {
        const int r0 = bT0 + q0 + wid * 16 + (lid >> 2);
#pragma unroll
        for (int kc = 0; kc < 4; kc++) {
            const int c0 = h * 64 + kc * 16 + (lid & 3) * 2;
            const size_t o00 = (size_t)r0 * QKV_N + c0;
            const size_t o10 = o00 + 8 * QKV_N;
            qfh[kc][0] = *reinterpret_cast<const uint32_t*>(qh_g + o00);
            qfh[kc][1] = *reinterpret_cast<const uint32_t*>(qh_g + o10);
            qfh[kc][2] = *reinterpret_cast<const uint32_t*>(qh_g + o00 + 8);
            qfh[kc][3] = *reinterpret_cast<const uint32_t*>(qh_g + o10 + 8);
            qfl[kc][0] = *reinterpret_cast<const uint32_t*>(ql_g + o00);
            qfl[kc][1] = *reinterpret_cast<const uint32_t*>(ql_g + o10);
            qfl[kc][2] = *reinterpret_cast<const uint32_t*>(ql_g + o00 + 8);
            qfl[kc][3] = *reinterpret_cast<const uint32_t*>(ql_g + o10 + 8);
        }
    }

    float o[8][4];
#pragma unroll
    for (int j = 0; j < 8; j++)
#pragma unroll
        for (int q = 0; q < 4; q++) o[j][q] = 0.f;
    float m0r = -1e30f, m1r = -1e30f, l0r = 0.f, l1r = 0.f;

    // K/V hi-only tile loader: 2 tiles x 64 rows x 8 groups = 1024 jobs / 128 thr
#define ISSUE_KT(KT)                                                            \
    do {                                                                        \
        const uint32_t _sb = abase + ((KT) % 3) * ASTG_B;                       \
        const int _kv0 = (KT) * 64;                                             \
        _Pragma("unroll")                                                       \
        for (int _r = 0; _r < 8; _r++) {                                        \
            const int _j    = tid + _r * 128;                                   \
            const int _tile = _j >> 9;                                          \
            const int _rem  = _j & 511;                                         \
            const int _row  = _rem >> 3;                                        \
            const int _g    = _rem & 7;                                         \
            const size_t _go = (size_t)(bT0 + _kv0 + _row) * QKV_N              \
                               + C_ * (1 + _tile) + h * 64 + _g * 8;            \
            cp_async16(_sb + _tile * AKT_B + (uint32_t)(_row * 144 + _g * 16),  \
                       qh_g + _go);                                             \
        }                                                                       \
        CP_COMMIT();                                                            \
    } while (0)

    ISSUE_KT(0);
    if (nkt > 1) ISSUE_KT(1);

    const int qrow0 = q0 + wid * 16 + (lid >> 2);   // global q row (half 0)
    const int qrow1 = qrow0 + 8;

    for (int kt = 0; kt < nkt; kt++) {
        if (kt < nkt - 1) CP_WAIT1();
        else              CP_WAIT0();
        __syncthreads();
        if (kt + 2 < nkt) ISSUE_KT(kt + 2);

        const uint32_t sb = abase + (kt % 3) * ASTG_B;
        const int kv0 = kt * 64;

        // ---- S = (Qh+Ql) @ Kh^T ----
        float s[8][4];
#pragma unroll
        for (int jn = 0; jn < 8; jn++) {
#pragma unroll
            for (int q = 0; q < 4; q++) s[jn][q] = 0.f;
            const uint32_t aK = sb +
                (uint32_t)(((jn * 8 + (lid & 7)) * 72 + (lid >> 3) * 8) * 2);
            uint32_t khA[4], khB[4];
            ldm_x4(khA, aK);
            ldm_x4(khB, aK + 64);
            mma_f16(s[jn], qfh[0], &khA[0]);
            mma_f16(s[jn], qfh[1], &khA[2]);
            mma_f16(s[jn], qfh[2], &khB[0]);
            mma_f16(s[jn], qfh[3], &khB[2]);
            mma_f16(s[jn], qfl[0], &khA[0]);
            mma_f16(s[jn], qfl[1], &khA[2]);
            mma_f16(s[jn], qfl[2], &khB[0]);
            mma_f16(s[jn], qfl[3], &khB[2]);
        }

        // scale (log2 domain) + causal mask (diagonal ktile only)
        const bool need_mask = (kt == nkt - 1);
#pragma unroll
        for (int jn = 0; jn < 8; jn++) {
#pragma unroll
            for (int q = 0; q < 4; q++) s[jn][q] *= SCALE_L2E;
            if (need_mask) {
                const int c = kv0 + jn * 8 + (lid & 3) * 2;
                if (c > qrow0)     s[jn][0] = -1e30f;
                if (c + 1 > qrow0) s[jn][1] = -1e30f;
                if (c > qrow1)     s[jn][2] = -1e30f;
                if (c + 1 > qrow1) s[jn][3] = -1e30f;
            }
        }

        // ---- online softmax in log2 domain (rows qrow0, qrow1) ----
        float mx0 = s[0][0], mx1 = s[0][2];
#pragma unroll
        for (int jn = 0; jn < 8; jn++) {
            mx0 = fmaxf(mx0, fmaxf(s[jn][0], s[jn][1]));
            mx1 = fmaxf(mx1, fmaxf(s[jn][2], s[jn][3]));
        }
        mx0 = fmaxf(mx0, __shfl_xor_sync(0xffffffffu, mx0, 1));
        mx0 = fmaxf(mx0, __shfl_xor_sync(0xffffffffu, mx0, 2));
        mx1 = fmaxf(mx1, __shfl_xor_sync(0xffffffffu, mx1, 1));
        mx1 = fmaxf(mx1, __shfl_xor_sync(0xffffffffu, mx1, 2));
        const float mn0 = fmaxf(m0r, mx0);
        const float mn1 = fmaxf(m1r, mx1);
        const float cr0 = exp2f(m0r - mn0);
        const float cr1 = exp2f(m1r - mn1);
        float sm0 = 0.f, sm1 = 0.f;
#pragma unroll
        for (int jn = 0; jn < 8; jn++) {
            s[jn][0] = exp2f(s[jn][0] - mn0);
            s[jn][1] = exp2f(s[jn][1] - mn0);
            s[jn][2] = exp2f(s[jn][2] - mn1);
            s[jn][3] = exp2f(s[jn][3] - mn1);
            sm0 += s[jn][0] + s[jn][1];
            sm1 += s[jn][2] + s[jn][3];
        }
        sm0 += __shfl_xor_sync(0xffffffffu, sm0, 1);
        sm0 += __shfl_xor_sync(0xffffffffu, sm0, 2);
        sm1 += __shfl_xor_sync(0xffffffffu, sm1, 1);
        sm1 += __shfl_xor_sync(0xffffffffu, sm1, 2);
        l0r = l0r * cr0 + sm0;
        l1r = l1r * cr1 + sm1;
        m0r = mn0; m1r = mn1;
#pragma unroll
        for (int j = 0; j < 8; j++) {
            o[j][0] *= cr0; o[j][1] *= cr0;
            o[j][2] *= cr1; o[j][3] *= cr1;
        }

        // ---- P -> fp16 hi/lo A-fragments ----
        uint32_t ph[4][4], pl[4][4];
#pragma unroll
        for (int t = 0; t < 4; t++) {
            ph[t][0] = pack_f16x2(s[2 * t][1], s[2 * t][0]);
            ph[t][1] = pack_f16x2(s[2 * t][3], s[2 * t][2]);
            ph[t][2] = pack_f16x2(s[2 * t + 1][1], s[2 * t + 1][0]);
            ph[t][3] = pack_f16x2(s[2 * t + 1][3], s[2 * t + 1][2]);
            float2 u0 = unpack_f16x2(ph[t][0]);
            float2 u1 = unpack_f16x2(ph[t][1]);
            float2 u2 = unpack_f16x2(ph[t][2]);
            float2 u3 = unpack_f16x2(ph[t][3]);
            pl[t][0] = pack_f16x2(s[2 * t][1] - u0.y,     s[2 * t][0] - u0.x);
            pl[t][1] = pack_f16x2(s[2 * t][3] - u1.y,     s[2 * t][2] - u1.x);
            pl[t][2] = pack_f16x2(s[2 * t + 1][1] - u2.y, s[2 * t + 1][0] - u2.x);
            pl[t][3] = pack_f16x2(s[2 * t + 1][3] - u3.y, s[2 * t + 1][2] - u3.x);
        }

        // ---- O += (Ph+Pl) @ Vh ----
        const uint32_t vb = sb + AKT_B;
#pragma unroll
        for (int jp = 0; jp < 4; jp++) {
#pragma unroll
            for (int kc = 0; kc < 4; kc++) {
                const uint32_t aV = vb + (uint32_t)((
                    (kc * 16 + ((lid >> 3) & 1) * 8 + (lid & 7)) * 72 +
                    jp * 16 + (lid >> 4) * 8) * 2);
                uint32_t vh[4];
                ldm_x4_t(vh, aV);
                mma_f16(o[2 * jp],     ph[kc], &vh[0]);
                mma_f16(o[2 * jp + 1], ph[kc], &vh[2]);
                mma_f16(o[2 * jp],     pl[kc], &vh[0]);
                mma_f16(o[2 * jp + 1], pl[kc], &vh[2]);
            }
        }
    }
#undef ISSUE_KT

    // ---- epilogue: normalize, split to fp16 hi/lo, write ch/cl ----
    const float inv0 = 1.f / l0r;
    const float inv1 = 1.f / l1r;
    const size_t r0 = (size_t)(bT0 + qrow0) * C_;
    const size_t r1 = (size_t)(bT0 + qrow1) * C_;
#pragma unroll
    for (int jn = 0; jn < 8; jn++) {
        const int col = h * 64 + jn * 8 + (lid & 3) * 2;
        float e0 = o[jn][0] * inv0, e1 = o[jn][1] * inv0;
        float e2 = o[jn][2] * inv1, e3 = o[jn][3] * inv1;
        uint32_t h0 = pack_f16x2(e1, e0);
        uint32_t h1 = pack_f16x2(e3, e2);
        float2 u0 = unpack_f16x2(h0);
        float2 u1 = unpack_f16x2(h1);
        uint32_t l0 = pack_f16x2(e1 - u0.y, e0 - u0.x);
        uint32_t l1 = pack_f16x2(e3 - u1.y, e2 - u1.x);
        *reinterpret_cast<uint32_t*>(&ch_g[r0 + col]) = h0;
        *reinterpret_cast<uint32_t*>(&ch_g[r1 + col]) = h1;
        *reinterpret_cast<uint32_t*>(&cl_g[r0 + col]) = l0;
        *reinterpret_cast<uint32_t*>(&cl_g[r1 + col]) = l1;
    }
}

// ---------------------------------------------------------------------------
// kernel_launch
// ---------------------------------------------------------------------------
extern "C" void kernel_launch(void* const* d_in, const int* in_sizes, int n_in,
                              void* d_out, int out_size)
{
    const float* x      = (const float*)d_in[0];  // [B,T,C]
    const float* w_qkv  = (const float*)d_in[1];  // [3C,C]
    const float* w_proj = (const float*)d_in[2];  // [C,C]
    float* out = (float*)d_out;                   // [B,T,C]

    __half *xh, *xl, *wqh, *wph, *qh, *ql, *ch, *cl;
    cudaGetSymbolAddress((void**)&xh,  g_xh);
    cudaGetSymbolAddress((void**)&xl,  g_xl);
    cudaGetSymbolAddress((void**)&wqh, g_wqh);
    cudaGetSymbolAddress((void**)&wph, g_wph);
    cudaGetSymbolAddress((void**)&qh,  g_qh);
    cudaGetSymbolAddress((void**)&ql,  g_ql);
    cudaGetSymbolAddress((void**)&ch,  g_ch);
    cudaGetSymbolAddress((void**)&cl,  g_cl);

    cudaFuncSetAttribute(gemm_mma_f16x2<true>,
                         cudaFuncAttributeMaxDynamicSharedMemorySize, GEMM_SMEM);
    cudaFuncSetAttribute(gemm_mma_f16x2<false>,
                         cudaFuncAttributeMaxDynamicSharedMemorySize, GEMM_SMEM);
    cudaFuncSetAttribute(attn_mma,
                         cudaFuncAttributeMaxDynamicSharedMemorySize, ATT_SMEM);

    // Fused split/convert (one launch)
    prep_f16<<<(PREP_JOBS + 255) / 256, 256>>>(
        x, w_qkv, w_proj, xh, xl, wqh, wph);

    // 1) QKV projection -> split fp16 output (qh/ql; ql only for Q cols)
    dim3 g1(QKV_N / 128, M_ / 128);
    gemm_mma_f16x2<true><<<g1, 256, GEMM_SMEM>>>(
        xh, xl, wqh, nullptr, qh, ql, M_, QKV_N, C_);

    // 2) Tensor-core causal flash attention -> split fp16 ctx (ch/cl)
    dim3 g2(T_ / 64, B_ * H_);
    attn_mma<<<g2, 128, ATT_SMEM>>>(qh, ql, ch, cl);

    // 3) Output projection -> fp32 out
    dim3 g3(C_ / 128, M_ / 128);
    gemm_mma_f16x2<false><<<g3, 256, GEMM_SMEM>>>(
        ch, cl, wph, out, nullptr, nullptr, M_, C_, C_);
}

// round 12
// speedup vs baseline: 1.4179x; 1.0970x over previous
#include <cuda_runtime.h>
#include <cuda_fp16.h>
#include <cstdint>

// Problem constants
#define B_  4
#define T_  2048
#define C_  1024
#define H_  16
#define D_  64
#define M_  (B_ * T_)       // 8192 rows
#define QKV_N (3 * C_)      // 3072

// ---------------------------------------------------------------------------
// Scratch (device globals; no runtime allocation allowed)
// ---------------------------------------------------------------------------
__device__ __half g_xh[(size_t)M_ * C_],    g_xl[(size_t)M_ * C_];
__device__ __half g_wqh[(size_t)QKV_N * C_];
__device__ __half g_wph[(size_t)C_ * C_];
__device__ __half g_qh[(size_t)M_ * QKV_N], g_ql[(size_t)M_ * QKV_N];
__device__ __half g_ch[(size_t)M_ * C_],    g_cl[(size_t)M_ * C_];

// ---------------------------------------------------------------------------
// PTX helpers (all non-arch-gated sm_80/sm_90 instructions)
// ---------------------------------------------------------------------------
__device__ __forceinline__ uint32_t smem_u32(const void* p) {
    uint32_t a;
    asm("{ .reg .u64 t; cvta.to.shared.u64 t, %1; cvt.u32.u64 %0, t; }"
        : "=r"(a) : "l"(p));
    return a;
}
__device__ __forceinline__ void cp_async16(uint32_t s, const void* g) {
    asm volatile("cp.async.cg.shared.global [%0], [%1], 16;"
                 :: "r"(s), "l"(g) : "memory");
}
#define CP_COMMIT() asm volatile("cp.async.commit_group;" ::: "memory")
#define CP_WAIT0()  asm volatile("cp.async.wait_group 0;" ::: "memory")
#define CP_WAIT1()  asm volatile("cp.async.wait_group 1;" ::: "memory")

__device__ __forceinline__ void ldm_x4(uint32_t* r, uint32_t a) {
    asm volatile("ldmatrix.sync.aligned.m8n8.x4.shared.b16 {%0,%1,%2,%3}, [%4];"
        : "=r"(r[0]), "=r"(r[1]), "=r"(r[2]), "=r"(r[3]) : "r"(a));
}
__device__ __forceinline__ void ldm_x4_t(uint32_t* r, uint32_t a) {
    asm volatile("ldmatrix.sync.aligned.m8n8.x4.trans.shared.b16 {%0,%1,%2,%3}, [%4];"
        : "=r"(r[0]), "=r"(r[1]), "=r"(r[2]), "=r"(r[3]) : "r"(a));
}
__device__ __forceinline__ void mma_f16(float* d, const uint32_t* a, const uint32_t* b) {
    asm volatile(
        "mma.sync.aligned.m16n8k16.row.col.f32.f16.f16.f32 "
        "{%0,%1,%2,%3}, {%4,%5,%6,%7}, {%8,%9}, {%0,%1,%2,%3};"
        : "+f"(d[0]), "+f"(d[1]), "+f"(d[2]), "+f"(d[3])
        : "r"(a[0]), "r"(a[1]), "r"(a[2]), "r"(a[3]), "r"(b[0]), "r"(b[1]));
}
// pack two f32 -> f16x2 ({hi -> upper16, lo -> lower16})
__device__ __forceinline__ uint32_t pack_f16x2(float hi, float lo) {
    uint32_t d;
    asm("cvt.rn.f16x2.f32 %0, %1, %2;" : "=r"(d) : "f"(hi), "f"(lo));
    return d;
}
// unpack f16x2 -> float2 (.x = lower half, .y = upper half)
__device__ __forceinline__ float2 unpack_f16x2(uint32_t p) {
    __half2 h = *reinterpret_cast<__half2*>(&p);
    return __half22float2(h);
}

// ---------------------------------------------------------------------------
// Fused prep: x split (hi/lo) + w_qkv conv + w_proj conv in ONE launch.
// ---------------------------------------------------------------------------
#define NX_JOBS  (M_ * C_ / 4)
#define NWQ_JOBS (QKV_N * C_ / 4)
#define NWP_JOBS (C_ * C_ / 4)
#define PREP_JOBS (NX_JOBS + NWQ_JOBS + NWP_JOBS)

__global__ __launch_bounds__(256) void prep_f16(
    const float* __restrict__ x, const float* __restrict__ wq,
    const float* __restrict__ wp,
    __half* __restrict__ xh, __half* __restrict__ xl,
    __half* __restrict__ wqh, __half* __restrict__ wph)
{
    int i = blockIdx.x * blockDim.x + threadIdx.x;
    if (i >= PREP_JOBS) return;
    if (i < NX_JOBS) {
        float4 v = reinterpret_cast<const float4*>(x)[i];
        uint32_t h0 = pack_f16x2(v.y, v.x);
        uint32_t h1 = pack_f16x2(v.w, v.z);
        float2 u0 = unpack_f16x2(h0);
        float2 u1 = unpack_f16x2(h1);
        uint32_t l0 = pack_f16x2(v.y - u0.y, v.x - u0.x);
        uint32_t l1 = pack_f16x2(v.w - u1.y, v.z - u1.x);
        reinterpret_cast<uint2*>(xh)[i] = make_uint2(h0, h1);
        reinterpret_cast<uint2*>(xl)[i] = make_uint2(l0, l1);
    } else if (i < NX_JOBS + NWQ_JOBS) {
        int j = i - NX_JOBS;
        float4 v = reinterpret_cast<const float4*>(wq)[j];
        reinterpret_cast<uint2*>(wqh)[j] =
            make_uint2(pack_f16x2(v.y, v.x), pack_f16x2(v.w, v.z));
    } else {
        int j = i - NX_JOBS - NWQ_JOBS;
        float4 v = reinterpret_cast<const float4*>(wp)[j];
        reinterpret_cast<uint2*>(wph)[j] =
            make_uint2(pack_f16x2(v.y, v.x), pack_f16x2(v.w, v.z));
    }
}

// ---------------------------------------------------------------------------
// mma.sync fp16x2 GEMM: C[M,N] = (Ah+Al)[M,K] @ Bh[N,K]^T.
// 128x128 CTA tile, BK=64, 8 warps (2x4), warp tile 64x32.
// 2-stage cp.async pipeline; 2 CTAs/SM. Stage = Ah | Al | Bh (72-b16 rows).
// SPLIT=true: write fp16 hi/lo; for n0 >= C_ (K/V columns) BOTH the lo
// output AND the Al input pass are skipped — K/V hi is consumed as rounded
// fp16 downstream, so the dropped Al term is below the existing rounding.
// ---------------------------------------------------------------------------
#define TILE_B  18432                   // 128 rows * 72 b16 * 2B
#define STAGE_B (3 * TILE_B)            // 55296
#define GEMM_SMEM (2 * STAGE_B)         // 110592 (x2 CTAs = 216KB <= 228KB)

template <bool SPLIT>
__global__ __launch_bounds__(256, 2) void gemm_mma_f16x2(
    const __half* __restrict__ Ah, const __half* __restrict__ Al,
    const __half* __restrict__ Bh,
    float* __restrict__ Cf, __half* __restrict__ Ch,
    __half* __restrict__ Cl, int M, int N, int K)
{
    extern __shared__ char smc[];
    const uint32_t sbase = smem_u32(smc);
    const int tid = threadIdx.x;
    const int lid = tid & 31;
    const int wid = tid >> 5;
    const int wm  = wid >> 2;      // 0..1
    const int wn  = wid & 3;       // 0..3
    const int m0  = blockIdx.y * 128;
    const int n0  = blockIdx.x * 128;

    // Q columns need full (Ah+Al) precision; K/V columns are consumed as
    // rounded fp16 hi, so the Al pass is skipped there.
    const bool use_al = !SPLIT || (n0 < C_);

    float acc[4][4][4];
#pragma unroll
    for (int i = 0; i < 4; i++)
#pragma unroll
        for (int j = 0; j < 4; j++)
#pragma unroll
            for (int q = 0; q < 4; q++) acc[i][j][q] = 0.f;

    // ldmatrix per-thread base offsets (b16 units within a tile, stride 72)
    const int a_base = (wm * 64 + (lid & 15)) * 72 + ((lid >> 4) * 8);
    // B paired-x4 mapping: matrices [n0k0, n0k1, n1k0, n1k1]
    const int b_base = (wn * 32 + (lid & 7) + ((lid >> 4) * 8)) * 72 +
                       (((lid >> 3) & 1) * 8);
    const int NS = K / 64;

#define ISSUE_STAGE(S)                                                          \
    do {                                                                        \
        const int _kc = (S) * 64;                                               \
        const uint32_t _sb = sbase + ((S) & 1) * STAGE_B;                       \
        _Pragma("unroll")                                                       \
        for (int _r = 0; _r < 4; _r++) {                                        \
            const int _c   = tid + _r * 256;      /* 0..1023 */                 \
            const int _row = _c >> 3;             /* 0..127  */                 \
            const int _c8  = (_c & 7) * 8;        /* 0..56   */                 \
            const uint32_t _so = _sb + (uint32_t)((_row * 72 + _c8) * 2);       \
            const size_t _ga = (size_t)(m0 + _row) * K + _kc + _c8;             \
            const size_t _gb = (size_t)(n0 + _row) * K + _kc + _c8;             \
            cp_async16(_so,              Ah + _ga);                             \
            if (use_al) cp_async16(_so + TILE_B, Al + _ga);                     \
            cp_async16(_so + 2 * TILE_B, Bh + _gb);                             \
        }                                                                       \
        CP_COMMIT();                                                            \
    } while (0)

    ISSUE_STAGE(0);

    for (int s = 0; s < NS; s++) {
        CP_WAIT0();
        __syncthreads();
        if (s + 1 < NS) ISSUE_STAGE(s + 1);

        const uint32_t sb = sbase + (s & 1) * STAGE_B;
#pragma unroll
        for (int ks = 0; ks < 4; ks++) {
            uint32_t ah[4][4], al[4][4], b01[4], b23[4];
#pragma unroll
            for (int mi = 0; mi < 4; mi++) {
                const uint32_t ao = sb +
                    (uint32_t)((a_base + mi * 16 * 72 + ks * 16) * 2);
                ldm_x4(ah[mi], ao);
                if (use_al) ldm_x4(al[mi], ao + TILE_B);
            }
            {
                const uint32_t bo = sb + 2 * TILE_B +
                    (uint32_t)((b_base + ks * 16) * 2);
                ldm_x4(b01, bo);                       // n-chunks 0,1
                ldm_x4(b23, bo + 16 * 72 * 2);         // n-chunks 2,3
            }
            // hi pass
#pragma unroll
            for (int mi = 0; mi < 4; mi++) {
                mma_f16(acc[mi][0], ah[mi], &b01[0]);
                mma_f16(acc[mi][1], ah[mi], &b01[2]);
                mma_f16(acc[mi][2], ah[mi], &b23[0]);
                mma_f16(acc[mi][3], ah[mi], &b23[2]);
            }
            // lo pass (skipped for K/V columns)
            if (use_al) {
#pragma unroll
                for (int mi = 0; mi < 4; mi++) {
                    mma_f16(acc[mi][0], al[mi], &b01[0]);
                    mma_f16(acc[mi][1], al[mi], &b01[2]);
                    mma_f16(acc[mi][2], al[mi], &b23[0]);
                    mma_f16(acc[mi][3], al[mi], &b23[2]);
                }
            }
        }
    }
#undef ISSUE_STAGE

    const bool want_lo = SPLIT && (n0 < C_);   // lo of K/V cols is never read
#pragma unroll
    for (int mi = 0; mi < 4; mi++)
#pragma unroll
        for (int ni = 0; ni < 4; ni++) {
            const int row = m0 + wm * 64 + mi * 16 + (lid >> 2);
            const int col = n0 + wn * 32 + ni * 8 + (lid & 3) * 2;
            if (SPLIT) {
                uint32_t h0 = pack_f16x2(acc[mi][ni][1], acc[mi][ni][0]);
                uint32_t h1 = pack_f16x2(acc[mi][ni][3], acc[mi][ni][2]);
                *reinterpret_cast<uint32_t*>(&Ch[(size_t)row * N + col])       = h0;
                *reinterpret_cast<uint32_t*>(&Ch[(size_t)(row + 8) * N + col]) = h1;
                if (want_lo) {
                    float2 u0 = unpack_f16x2(h0);
                    float2 u1 = unpack_f16x2(h1);
                    uint32_t l0 = pack_f16x2(acc[mi][ni][1] - u0.y,
                                             acc[mi][ni][0] - u0.x);
                    uint32_t l1 = pack_f16x2(acc[mi][ni][3] - u1.y,
                                             acc[mi][ni][2] - u1.x);
                    *reinterpret_cast<uint32_t*>(&Cl[(size_t)row * N + col])       = l0;
                    *reinterpret_cast<uint32_t*>(&Cl[(size_t)(row + 8) * N + col]) = l1;
                }
            } else {
                float2 v0 = make_float2(acc[mi][ni][0], acc[mi][ni][1]);
                float2 v1 = make_float2(acc[mi][ni][2], acc[mi][ni][3]);
                *reinterpret_cast<float2*>(&Cf[(size_t)row * N + col])       = v0;
                *reinterpret_cast<float2*>(&Cf[(size_t)(row + 8) * N + col]) = v1;
            }
        }
}

// ---------------------------------------------------------------------------
// Tensor-core causal flash attention, fp16x2 split precision (unchanged).
// CTA: 128 thr (4 warps), 64-row Q tile per CTA -> 4 CTAs/SM.
// K/V 64-row hi-only tiles, 3-stage cp.async pipeline.
// Softmax in log2 domain: scale = 0.125*log2(e), exp2f.
// ---------------------------------------------------------------------------
#define AKT_B   9216                 // 64 rows * 72 b16 * 2B
#define ASTG_B  (2 * AKT_B)          // Kh | Vh
#define ATT_SMEM (3 * ASTG_B)        // 55296 (x4 CTAs = 216KB <= 228KB)
#define SCALE_L2E 0.1803368801111204f   // 0.125 * log2(e)

__global__ __launch_bounds__(128, 4) void attn_mma(
    const __half* __restrict__ qh_g, const __half* __restrict__ ql_g,
    __half* __restrict__ ch_g, __half* __restrict__ cl_g)
{
    extern __shared__ char smc[];
    const uint32_t abase = smem_u32(smc);
    const int tid = threadIdx.x;
    const int lid = tid & 31;
    const int wid = tid >> 5;
    const int qi  = (int)gridDim.x - 1 - (int)blockIdx.x;  // long CTAs first
    const int bh  = blockIdx.y;
    const int b   = bh >> 4;
    const int h   = bh & 15;
    const int q0  = qi * 64;
    const int bT0 = b * T_;
    const int nkt = qi + 1;

    // ---- Q fragments (hi/lo), loaded once from global ----
    uint32_t qfh[4][4], qfl[4][4];
    {
        const int r0 = bT0 + q0 + wid * 16 + (lid >> 2);
#pragma unroll
        for (int kc = 0; kc < 4; kc++) {
            const int c0 = h * 64 + kc * 16 + (lid & 3) * 2;
            const size_t o00 = (size_t)r0 * QKV_N + c0;
            const size_t o10 = o00 + 8 * QKV_N;
            qfh[kc][0] = *reinterpret_cast<const uint32_t*>(qh_g + o00);
            qfh[kc][1] = *reinterpret_cast<const uint32_t*>(qh_g + o10);
            qfh[kc][2] = *reinterpret_cast<const uint32_t*>(qh_g + o00 + 8);
            qfh[kc][3] = *reinterpret_cast<const uint32_t*>(qh_g + o10 + 8);
            qfl[kc][0] = *reinterpret_cast<const uint32_t*>(ql_g + o00);
            qfl[kc][1] = *reinterpret_cast<const uint32_t*>(ql_g + o10);
            qfl[kc][2] = *reinterpret_cast<const uint32_t*>(ql_g + o00 + 8);
            qfl[kc][3] = *reinterpret_cast<const uint32_t*>(ql_g + o10 + 8);
        }
    }

    float o[8][4];
#pragma unroll
    for (int j = 0; j < 8; j++)
#pragma unroll
        for (int q = 0; q < 4; q++) o[j][q] = 0.f;
    float m0r = -1e30f, m1r = -1e30f, l0r = 0.f, l1r = 0.f;

    // K/V hi-only tile loader: 2 tiles x 64 rows x 8 groups = 1024 jobs / 128 thr
#define ISSUE_KT(KT)                                                            \
    do {                                                                        \
        const uint32_t _sb = abase + ((KT) % 3) * ASTG_B;                       \
        const int _kv0 = (KT) * 64;                                             \
        _Pragma("unroll")                                                       \
        for (int _r = 0; _r < 8; _r++) {                                        \
            const int _j    = tid + _r * 128;                                   \
            const int _tile = _j >> 9;                                          \
            const int _rem  = _j & 511;                                         \
            const int _row  = _rem >> 3;                                        \
            const int _g    = _rem & 7;                                         \
            const size_t _go = (size_t)(bT0 + _kv0 + _row) * QKV_N              \
                               + C_ * (1 + _tile) + h * 64 + _g * 8;            \
            cp_async16(_sb + _tile * AKT_B + (uint32_t)(_row * 144 + _g * 16),  \
                       qh_g + _go);                                             \
        }                                                                       \
        CP_COMMIT();                                                            \
    } while (0)

    ISSUE_KT(0);
    if (nkt > 1) ISSUE_KT(1);

    const int qrow0 = q0 + wid * 16 + (lid >> 2);   // global q row (half 0)
    const int qrow1 = qrow0 + 8;

    for (int kt = 0; kt < nkt; kt++) {
        if (kt < nkt - 1) CP_WAIT1();
        else              CP_WAIT0();
        __syncthreads();
        if (kt + 2 < nkt) ISSUE_KT(kt + 2);

        const uint32_t sb = abase + (kt % 3) * ASTG_B;
        const int kv0 = kt * 64;

        // ---- S = (Qh+Ql) @ Kh^T ----
        float s[8][4];
#pragma unroll
        for (int jn = 0; jn < 8; jn++) {
#pragma unroll
            for (int q = 0; q < 4; q++) s[jn][q] = 0.f;
            const uint32_t aK = sb +
                (uint32_t)(((jn * 8 + (lid & 7)) * 72 + (lid >> 3) * 8) * 2);
            uint32_t khA[4], khB[4];
            ldm_x4(khA, aK);
            ldm_x4(khB, aK + 64);
            mma_f16(s[jn], qfh[0], &khA[0]);
            mma_f16(s[jn], qfh[1], &khA[2]);
            mma_f16(s[jn], qfh[2], &khB[0]);
            mma_f16(s[jn], qfh[3], &khB[2]);
            mma_f16(s[jn], qfl[0], &khA[0]);
            mma_f16(s[jn], qfl[1], &khA[2]);
            mma_f16(s[jn], qfl[2], &khB[0]);
            mma_f16(s[jn], qfl[3], &khB[2]);
        }

        // scale (log2 domain) + causal mask (diagonal ktile only)
        const bool need_mask = (kt == nkt - 1);
#pragma unroll
        for (int jn = 0; jn < 8; jn++) {
#pragma unroll
            for (int q = 0; q < 4; q++) s[jn][q] *= SCALE_L2E;
            if (need_mask) {
                const int c = kv0 + jn * 8 + (lid & 3) * 2;
                if (c > qrow0)     s[jn][0] = -1e30f;
                if (c + 1 > qrow0) s[jn][1] = -1e30f;
                if (c > qrow1)     s[jn][2] = -1e30f;
                if (c + 1 > qrow1) s[jn][3] = -1e30f;
            }
        }

        // ---- online softmax in log2 domain (rows qrow0, qrow1) ----
        float mx0 = s[0][0], mx1 = s[0][2];
#pragma unroll
        for (int jn = 0; jn < 8; jn++) {
            mx0 = fmaxf(mx0, fmaxf(s[jn][0], s[jn][1]));
            mx1 = fmaxf(mx1, fmaxf(s[jn][2], s[jn][3]));
        }
        mx0 = fmaxf(mx0, __shfl_xor_sync(0xffffffffu, mx0, 1));
        mx0 = fmaxf(mx0, __shfl_xor_sync(0xffffffffu, mx0, 2));
        mx1 = fmaxf(mx1, __shfl_xor_sync(0xffffffffu, mx1, 1));
        mx1 = fmaxf(mx1, __shfl_xor_sync(0xffffffffu, mx1, 2));
        const float mn0 = fmaxf(m0r, mx0);
        const float mn1 = fmaxf(m1r, mx1);
        const float cr0 = exp2f(m0r - mn0);
        const float cr1 = exp2f(m1r - mn1);
        float sm0 = 0.f, sm1 = 0.f;
#pragma unroll
        for (int jn = 0; jn < 8; jn++) {
            s[jn][0] = exp2f(s[jn][0] - mn0);
            s[jn][1] = exp2f(s[jn][1] - mn0);
            s[jn][2] = exp2f(s[jn][2] - mn1);
            s[jn][3] = exp2f(s[jn][3] - mn1);
            sm0 += s[jn][0] + s[jn][1];
            sm1 += s[jn][2] + s[jn][3];
        }
        sm0 += __shfl_xor_sync(0xffffffffu, sm0, 1);
        sm0 += __shfl_xor_sync(0xffffffffu, sm0, 2);
        sm1 += __shfl_xor_sync(0xffffffffu, sm1, 1);
        sm1 += __shfl_xor_sync(0xffffffffu, sm1, 2);
        l0r = l0r * cr0 + sm0;
        l1r = l1r * cr1 + sm1;
        m0r = mn0; m1r = mn1;
#pragma unroll
        for (int j = 0; j < 8; j++) {
            o[j][0] *= cr0; o[j][1] *= cr0;
            o[j][2] *= cr1; o[j][3] *= cr1;
        }

        // ---- P -> fp16 hi/lo A-fragments ----
        uint32_t ph[4][4], pl[4][4];
#pragma unroll
        for (int t = 0; t < 4; t++) {
            ph[t][0] = pack_f16x2(s[2 * t][1], s[2 * t][0]);
            ph[t][1] = pack_f16x2(s[2 * t][3], s[2 * t][2]);
            ph[t][2] = pack_f16x2(s[2 * t + 1][1], s[2 * t + 1][0]);
            ph[t][3] = pack_f16x2(s[2 * t + 1][3], s[2 * t + 1][2]);
            float2 u0 = unpack_f16x2(ph[t][0]);
            float2 u1 = unpack_f16x2(ph[t][1]);
            float2 u2 = unpack_f16x2(ph[t][2]);
            float2 u3 = unpack_f16x2(ph[t][3]);
            pl[t][0] = pack_f16x2(s[2 * t][1] - u0.y,     s[2 * t][0] - u0.x);
            pl[t][1] = pack_f16x2(s[2 * t][3] - u1.y,     s[2 * t][2] - u1.x);
            pl[t][2] = pack_f16x2(s[2 * t + 1][1] - u2.y, s[2 * t + 1][0] - u2.x);
            pl[t][3] = pack_f16x2(s[2 * t + 1][3] - u3.y, s[2 * t + 1][2] - u3.x);
        }

        // ---- O += (Ph+Pl) @ Vh ----
        const uint32_t vb = sb + AKT_B;
#pragma unroll
        for (int jp = 0; jp < 4; jp++) {
#pragma unroll
            for (int kc = 0; kc < 4; kc++) {
                const uint32_t aV = vb + (uint32_t)((
                    (kc * 16 + ((lid >> 3) & 1) * 8 + (lid & 7)) * 72 +
                    jp * 16 + (lid >> 4) * 8) * 2);
                uint32_t vh[4];
                ldm_x4_t(vh, aV);
                mma_f16(o[2 * jp],     ph[kc], &vh[0]);
                mma_f16(o[2 * jp + 1], ph[kc], &vh[2]);
                mma_f16(o[2 * jp],     pl[kc], &vh[0]);
                mma_f16(o[2 * jp + 1], pl[kc], &vh[2]);
            }
        }
    }
#undef ISSUE_KT

    // ---- epilogue: normalize, split to fp16 hi/lo, write ch/cl ----
    const float inv0 = 1.f / l0r;
    const float inv1 = 1.f / l1r;
    const size_t r0 = (size_t)(bT0 + qrow0) * C_;
    const size_t r1 = (size_t)(bT0 + qrow1) * C_;
#pragma unroll
    for (int jn = 0; jn < 8; jn++) {
        const int col = h * 64 + jn * 8 + (lid & 3) * 2;
        float e0 = o[jn][0] * inv0, e1 = o[jn][1] * inv0;
        float e2 = o[jn][2] * inv1, e3 = o[jn][3] * inv1;
        uint32_t h0 = pack_f16x2(e1, e0);
        uint32_t h1 = pack_f16x2(e3, e2);
        float2 u0 = unpack_f16x2(h0);
        float2 u1 = unpack_f16x2(h1);
        uint32_t l0 = pack_f16x2(e1 - u0.y, e0 - u0.x);
        uint32_t l1 = pack_f16x2(e3 - u1.y, e2 - u1.x);
        *reinterpret_cast<uint32_t*>(&ch_g[r0 + col]) = h0;
        *reinterpret_cast<uint32_t*>(&ch_g[r1 + col]) = h1;
        *reinterpret_cast<uint32_t*>(&cl_g[r0 + col]) = l0;
        *reinterpret_cast<uint32_t*>(&cl_g[r1 + col]) = l1;
    }
}

// ---------------------------------------------------------------------------
// kernel_launch
// ---------------------------------------------------------------------------
extern "C" void kernel_launch(void* const* d_in, const int* in_sizes, int n_in,
                              void* d_out, int out_size)
{
    const float* x      = (const float*)d_in[0];  // [B,T,C]
    const float* w_qkv  = (const float*)d_in[1];  // [3C,C]
    const float* w_proj = (const float*)d_in[2];  // [C,C]
    float* out = (float*)d_out;                   // [B,T,C]

    __half *xh, *xl, *wqh, *wph, *qh, *ql, *ch, *cl;
    cudaGetSymbolAddress((void**)&xh,  g_xh);
    cudaGetSymbolAddress((void**)&xl,  g_xl);
    cudaGetSymbolAddress((void**)&wqh, g_wqh);
    cudaGetSymbolAddress((void**)&wph, g_wph);
    cudaGetSymbolAddress((void**)&qh,  g_qh);
    cudaGetSymbolAddress((void**)&ql,  g_ql);
    cudaGetSymbolAddress((void**)&ch,  g_ch);
    cudaGetSymbolAddress((void**)&cl,  g_cl);

    cudaFuncSetAttribute(gemm_mma_f16x2<true>,
                         cudaFuncAttributeMaxDynamicSharedMemorySize, GEMM_SMEM);
    cudaFuncSetAttribute(gemm_mma_f16x2<false>,
                         cudaFuncAttributeMaxDynamicSharedMemorySize, GEMM_SMEM);
    cudaFuncSetAttribute(attn_mma,
                         cudaFuncAttributeMaxDynamicSharedMemorySize, ATT_SMEM);

    // Fused split/convert (one launch)
    prep_f16<<<(PREP_JOBS + 255) / 256, 256>>>(
        x, w_qkv, w_proj, xh, xl, wqh, wph);

    // 1) QKV projection -> split fp16 output (Q full precision; K/V hi-only)
    dim3 g1(QKV_N / 128, M_ / 128);
    gemm_mma_f16x2<true><<<g1, 256, GEMM_SMEM>>>(
        xh, xl, wqh, nullptr, qh, ql, M_, QKV_N, C_);

    // 2) Tensor-core causal flash attention -> split fp16 ctx (ch/cl)
    dim3 g2(T_ / 64, B_ * H_);
    attn_mma<<<g2, 128, ATT_SMEM>>>(qh, ql, ch, cl);

    // 3) Output projection -> fp32 out
    dim3 g3(C_ / 128, M_ / 128);
    gemm_mma_f16x2<false><<<g3, 256, GEMM_SMEM>>>(
        ch, cl, wph, out, nullptr, nullptr, M_, C_, C_);
}

// round 13
// speedup vs baseline: 1.9529x; 1.3773x over previous
#include <cuda_runtime.h>
#include <cuda_fp16.h>
#include <cstdint>

// Problem constants
#define B_  4
#define T_  2048
#define C_  1024
#define H_  16
#define D_  64
#define M_  (B_ * T_)       // 8192 rows
#define QKV_N (3 * C_)      // 3072

// ---------------------------------------------------------------------------
// Scratch (device globals; no runtime allocation allowed)
// ---------------------------------------------------------------------------
__device__ __half g_xh[(size_t)M_ * C_];
__device__ __half g_wqh[(size_t)QKV_N * C_];
__device__ __half g_wph[(size_t)C_ * C_];
__device__ __half g_qh[(size_t)M_ * QKV_N];
__device__ __half g_ch[(size_t)M_ * C_];

// ---------------------------------------------------------------------------
// PTX helpers (all non-arch-gated sm_80/sm_90 instructions)
// ---------------------------------------------------------------------------
__device__ __forceinline__ uint32_t smem_u32(const void* p) {
    uint32_t a;
    asm("{ .reg .u64 t; cvta.to.shared.u64 t, %1; cvt.u32.u64 %0, t; }"
        : "=r"(a) : "l"(p));
    return a;
}
__device__ __forceinline__ void cp_async16(uint32_t s, const void* g) {
    asm volatile("cp.async.cg.shared.global [%0], [%1], 16;"
                 :: "r"(s), "l"(g) : "memory");
}
#define CP_COMMIT() asm volatile("cp.async.commit_group;" ::: "memory")
#define CP_WAIT0()  asm volatile("cp.async.wait_group 0;" ::: "memory")
#define CP_WAIT1()  asm volatile("cp.async.wait_group 1;" ::: "memory")

__device__ __forceinline__ void ldm_x4(uint32_t* r, uint32_t a) {
    asm volatile("ldmatrix.sync.aligned.m8n8.x4.shared.b16 {%0,%1,%2,%3}, [%4];"
        : "=r"(r[0]), "=r"(r[1]), "=r"(r[2]), "=r"(r[3]) : "r"(a));
}
__device__ __forceinline__ void ldm_x4_t(uint32_t* r, uint32_t a) {
    asm volatile("ldmatrix.sync.aligned.m8n8.x4.trans.shared.b16 {%0,%1,%2,%3}, [%4];"
        : "=r"(r[0]), "=r"(r[1]), "=r"(r[2]), "=r"(r[3]) : "r"(a));
}
__device__ __forceinline__ void mma_f16(float* d, const uint32_t* a, const uint32_t* b) {
    asm volatile(
        "mma.sync.aligned.m16n8k16.row.col.f32.f16.f16.f32 "
        "{%0,%1,%2,%3}, {%4,%5,%6,%7}, {%8,%9}, {%0,%1,%2,%3};"
        : "+f"(d[0]), "+f"(d[1]), "+f"(d[2]), "+f"(d[3])
        : "r"(a[0]), "r"(a[1]), "r"(a[2]), "r"(a[3]), "r"(b[0]), "r"(b[1]));
}
// pack two f32 -> f16x2 ({hi -> upper16, lo -> lower16})
__device__ __forceinline__ uint32_t pack_f16x2(float hi, float lo) {
    uint32_t d;
    asm("cvt.rn.f16x2.f32 %0, %1, %2;" : "=r"(d) : "f"(hi), "f"(lo));
    return d;
}
// unpack f16x2 -> float2 (.x = lower half, .y = upper half)
__device__ __forceinline__ float2 unpack_f16x2(uint32_t p) {
    __half2 h = *reinterpret_cast<__half2*>(&p);
    return __half22float2(h);
}

// ---------------------------------------------------------------------------
// Fused prep: convert x, w_qkv, w_proj to fp16 in ONE launch.
// ---------------------------------------------------------------------------
#define NX_JOBS  (M_ * C_ / 4)
#define NWQ_JOBS (QKV_N * C_ / 4)
#define NWP_JOBS (C_ * C_ / 4)
#define PREP_JOBS (NX_JOBS + NWQ_JOBS + NWP_JOBS)

__global__ __launch_bounds__(256) void prep_f16(
    const float* __restrict__ x, const float* __restrict__ wq,
    const float* __restrict__ wp,
    __half* __restrict__ xh, __half* __restrict__ wqh, __half* __restrict__ wph)
{
    int i = blockIdx.x * blockDim.x + threadIdx.x;
    if (i >= PREP_JOBS) return;
    const float* src;
    __half* dst;
    int j;
    if (i < NX_JOBS)                    { src = x;  dst = xh;  j = i; }
    else if (i < NX_JOBS + NWQ_JOBS)    { src = wq; dst = wqh; j = i - NX_JOBS; }
    else                                { src = wp; dst = wph; j = i - NX_JOBS - NWQ_JOBS; }
    float4 v = reinterpret_cast<const float4*>(src)[j];
    reinterpret_cast<uint2*>(dst)[j] =
        make_uint2(pack_f16x2(v.y, v.x), pack_f16x2(v.w, v.z));
}

// ---------------------------------------------------------------------------
// mma.sync fp16 GEMM: C[M,N] = Ah[M,K] @ Bh[N,K]^T (single pass).
// 128x128 CTA tile, BK=64, 8 warps (2x4), warp tile 64x32.
// 2-stage cp.async pipeline; 2 CTAs/SM. Stage = Ah | Bh (72-b16 rows).
// OUTH=true: write fp16; else fp32.
// ---------------------------------------------------------------------------
#define TILE_B  18432                   // 128 rows * 72 b16 * 2B
#define STAGE_B (2 * TILE_B)            // 36864
#define GEMM_SMEM (2 * STAGE_B)         // 73728 (x2 CTAs = 144KB <= 228KB)

template <bool OUTH>
__global__ __launch_bounds__(256, 2) void gemm_mma_f16(
    const __half* __restrict__ Ah, const __half* __restrict__ Bh,
    float* __restrict__ Cf, __half* __restrict__ Ch, int M, int N, int K)
{
    extern __shared__ char smc[];
    const uint32_t sbase = smem_u32(smc);
    const int tid = threadIdx.x;
    const int lid = tid & 31;
    const int wid = tid >> 5;
    const int wm  = wid >> 2;      // 0..1
    const int wn  = wid & 3;       // 0..3
    const int m0  = blockIdx.y * 128;
    const int n0  = blockIdx.x * 128;

    float acc[4][4][4];
#pragma unroll
    for (int i = 0; i < 4; i++)
#pragma unroll
        for (int j = 0; j < 4; j++)
#pragma unroll
            for (int q = 0; q < 4; q++) acc[i][j][q] = 0.f;

    // ldmatrix per-thread base offsets (b16 units within a tile, stride 72)
    const int a_base = (wm * 64 + (lid & 15)) * 72 + ((lid >> 4) * 8);
    // B paired-x4 mapping: matrices [n0k0, n0k1, n1k0, n1k1]
    const int b_base = (wn * 32 + (lid & 7) + ((lid >> 4) * 8)) * 72 +
                       (((lid >> 3) & 1) * 8);
    const int NS = K / 64;

#define ISSUE_STAGE(S)                                                          \
    do {                                                                        \
        const int _kc = (S) * 64;                                               \
        const uint32_t _sb = sbase + ((S) & 1) * STAGE_B;                       \
        _Pragma("unroll")                                                       \
        for (int _r = 0; _r < 4; _r++) {                                        \
            const int _c   = tid + _r * 256;      /* 0..1023 */                 \
            const int _row = _c >> 3;             /* 0..127  */                 \
            const int _c8  = (_c & 7) * 8;        /* 0..56   */                 \
            const uint32_t _so = _sb + (uint32_t)((_row * 72 + _c8) * 2);       \
            cp_async16(_so,          Ah + (size_t)(m0 + _row) * K + _kc + _c8); \
            cp_async16(_so + TILE_B, Bh + (size_t)(n0 + _row) * K + _kc + _c8); \
        }                                                                       \
        CP_COMMIT();                                                            \
    } while (0)

    ISSUE_STAGE(0);

    for (int s = 0; s < NS; s++) {
        CP_WAIT0();
        __syncthreads();
        if (s + 1 < NS) ISSUE_STAGE(s + 1);

        const uint32_t sb = sbase + (s & 1) * STAGE_B;
#pragma unroll
        for (int ks = 0; ks < 4; ks++) {
            uint32_t ah[4][4], b01[4], b23[4];
#pragma unroll
            for (int mi = 0; mi < 4; mi++) {
                const uint32_t ao = sb +
                    (uint32_t)((a_base + mi * 16 * 72 + ks * 16) * 2);
                ldm_x4(ah[mi], ao);
            }
            {
                const uint32_t bo = sb + TILE_B +
                    (uint32_t)((b_base + ks * 16) * 2);
                ldm_x4(b01, bo);                       // n-chunks 0,1
                ldm_x4(b23, bo + 16 * 72 * 2);         // n-chunks 2,3
            }
#pragma unroll
            for (int mi = 0; mi < 4; mi++) {
                mma_f16(acc[mi][0], ah[mi], &b01[0]);
                mma_f16(acc[mi][1], ah[mi], &b01[2]);
                mma_f16(acc[mi][2], ah[mi], &b23[0]);
                mma_f16(acc[mi][3], ah[mi], &b23[2]);
            }
        }
    }
#undef ISSUE_STAGE

#pragma unroll
    for (int mi = 0; mi < 4; mi++)
#pragma unroll
        for (int ni = 0; ni < 4; ni++) {
            const int row = m0 + wm * 64 + mi * 16 + (lid >> 2);
            const int col = n0 + wn * 32 + ni * 8 + (lid & 3) * 2;
            if (OUTH) {
                uint32_t h0 = pack_f16x2(acc[mi][ni][1], acc[mi][ni][0]);
                uint32_t h1 = pack_f16x2(acc[mi][ni][3], acc[mi][ni][2]);
                *reinterpret_cast<uint32_t*>(&Ch[(size_t)row * N + col])       = h0;
                *reinterpret_cast<uint32_t*>(&Ch[(size_t)(row + 8) * N + col]) = h1;
            } else {
                float2 v0 = make_float2(acc[mi][ni][0], acc[mi][ni][1]);
                float2 v1 = make_float2(acc[mi][ni][2], acc[mi][ni][3]);
                *reinterpret_cast<float2*>(&Cf[(size_t)row * N + col])       = v0;
                *reinterpret_cast<float2*>(&Cf[(size_t)(row + 8) * N + col]) = v1;
            }
        }
}

// ---------------------------------------------------------------------------
// Tensor-core causal flash attention.
// Q, K, V consumed as rounded fp16 (hi-only). P kept split hi/lo (cheap,
// protects the O accumulation). Output ctx written as fp16 hi-only.
// CTA: 128 thr (4 warps), 64-row Q tile per CTA -> 4 CTAs/SM.
// K/V 64-row tiles, 3-stage cp.async pipeline. Softmax in log2 domain.
// ---------------------------------------------------------------------------
#define AKT_B   9216                 // 64 rows * 72 b16 * 2B
#define ASTG_B  (2 * AKT_B)          // Kh | Vh
#define ATT_SMEM (3 * ASTG_B)        // 55296 (x4 CTAs = 216KB <= 228KB)
#define SCALE_L2E 0.1803368801111204f   // 0.125 * log2(e)

__global__ __launch_bounds__(128, 4) void attn_mma(
    const __half* __restrict__ qh_g, __half* __restrict__ ch_g)
{
    extern __shared__ char smc[];
    const uint32_t abase = smem_u32(smc);
    const int tid = threadIdx.x;
    const int lid = tid & 31;
    const int wid = tid >> 5;
    const int qi  = (int)gridDim.x - 1 - (int)blockIdx.x;  // long CTAs first
    const int bh  = blockIdx.y;
    const int b   = bh >> 4;
    const int h   = bh & 15;
    const int q0  = qi * 64;
    const int bT0 = b * T_;
    const int nkt = qi + 1;

    // ---- Q fragments (hi only), loaded once from global ----
    uint32_t qfh[4][4];
    {
        const int r0 = bT0 + q0 + wid * 16 + (lid >> 2);
#pragma unroll
        for (int kc = 0; kc < 4; kc++) {
            const int c0 = h * 64 + kc * 16 + (lid & 3) * 2;
            const size_t o00 = (size_t)r0 * QKV_N + c0;
            const size_t o10 = o00 + 8 * QKV_N;
            qfh[kc][0] = *reinterpret_cast<const uint32_t*>(qh_g + o00);
            qfh[kc][1] = *reinterpret_cast<const uint32_t*>(qh_g + o10);
            qfh[kc][2] = *reinterpret_cast<const uint32_t*>(qh_g + o00 + 8);
            qfh[kc][3] = *reinterpret_cast<const uint32_t*>(qh_g + o10 + 8);
        }
    }

    float o[8][4];
#pragma unroll
    for (int j = 0; j < 8; j++)
#pragma unroll
        for (int q = 0; q < 4; q++) o[j][q] = 0.f;
    float m0r = -1e30f, m1r = -1e30f, l0r = 0.f, l1r = 0.f;

    // K/V tile loader: 2 tiles x 64 rows x 8 groups = 1024 jobs / 128 thr
#define ISSUE_KT(KT)                                                            \
    do {                                                                        \
        const uint32_t _sb = abase + ((KT) % 3) * ASTG_B;                       \
        const int _kv0 = (KT) * 64;                                             \
        _Pragma("unroll")                                                       \
        for (int _r = 0; _r < 8; _r++) {                                        \
            const int _j    = tid + _r * 128;                                   \
            const int _tile = _j >> 9;                                          \
            const int _rem  = _j & 511;                                         \
            const int _row  = _rem >> 3;                                        \
            const int _g    = _rem & 7;                                         \
            const size_t _go = (size_t)(bT0 + _kv0 + _row) * QKV_N              \
                               + C_ * (1 + _tile) + h * 64 + _g * 8;            \
            cp_async16(_sb + _tile * AKT_B + (uint32_t)(_row * 144 + _g * 16),  \
                       qh_g + _go);                                             \
        }                                                                       \
        CP_COMMIT();                                                            \
    } while (0)

    ISSUE_KT(0);
    if (nkt > 1) ISSUE_KT(1);

    const int qrow0 = q0 + wid * 16 + (lid >> 2);   // global q row (half 0)
    const int qrow1 = qrow0 + 8;

    for (int kt = 0; kt < nkt; kt++) {
        if (kt < nkt - 1) CP_WAIT1();
        else              CP_WAIT0();
        __syncthreads();
        if (kt + 2 < nkt) ISSUE_KT(kt + 2);

        const uint32_t sb = abase + (kt % 3) * ASTG_B;
        const int kv0 = kt * 64;

        // ---- S = Qh @ Kh^T ----
        float s[8][4];
#pragma unroll
        for (int jn = 0; jn < 8; jn++) {
#pragma unroll
            for (int q = 0; q < 4; q++) s[jn][q] = 0.f;
            const uint32_t aK = sb +
                (uint32_t)(((jn * 8 + (lid & 7)) * 72 + (lid >> 3) * 8) * 2);
            uint32_t khA[4], khB[4];
            ldm_x4(khA, aK);
            ldm_x4(khB, aK + 64);
            mma_f16(s[jn], qfh[0], &khA[0]);
            mma_f16(s[jn], qfh[1], &khA[2]);
            mma_f16(s[jn], qfh[2], &khB[0]);
            mma_f16(s[jn], qfh[3], &khB[2]);
        }

        // scale (log2 domain) + causal mask (diagonal ktile only)
        const bool need_mask = (kt == nkt - 1);
#pragma unroll
        for (int jn = 0; jn < 8; jn++) {
#pragma unroll
            for (int q = 0; q < 4; q++) s[jn][q] *= SCALE_L2E;
            if (need_mask) {
                const int c = kv0 + jn * 8 + (lid & 3) * 2;
                if (c > qrow0)     s[jn][0] = -1e30f;
                if (c + 1 > qrow0) s[jn][1] = -1e30f;
                if (c > qrow1)     s[jn][2] = -1e30f;
                if (c + 1 > qrow1) s[jn][3] = -1e30f;
            }
        }

        // ---- online softmax in log2 domain (rows qrow0, qrow1) ----
        float mx0 = s[0][0], mx1 = s[0][2];
#pragma unroll
        for (int jn = 0; jn < 8; jn++) {
            mx0 = fmaxf(mx0, fmaxf(s[jn][0], s[jn][1]));
            mx1 = fmaxf(mx1, fmaxf(s[jn][2], s[jn][3]));
        }
        mx0 = fmaxf(mx0, __shfl_xor_sync(0xffffffffu, mx0, 1));
        mx0 = fmaxf(mx0, __shfl_xor_sync(0xffffffffu, mx0, 2));
        mx1 = fmaxf(mx1, __shfl_xor_sync(0xffffffffu, mx1, 1));
        mx1 = fmaxf(mx1, __shfl_xor_sync(0xffffffffu, mx1, 2));
        const float mn0 = fmaxf(m0r, mx0);
        const float mn1 = fmaxf(m1r, mx1);
        const float cr0 = exp2f(m0r - mn0);
        const float cr1 = exp2f(m1r - mn1);
        float sm0 = 0.f, sm1 = 0.f;
#pragma unroll
        for (int jn = 0; jn < 8; jn++) {
            s[jn][0] = exp2f(s[jn][0] - mn0);
            s[jn][1] = exp2f(s[jn][1] - mn0);
            s[jn][2] = exp2f(s[jn][2] - mn1);
            s[jn][3] = exp2f(s[jn][3] - mn1);
            sm0 += s[jn][0] + s[jn][1];
            sm1 += s[jn][2] + s[jn][3];
        }
        sm0 += __shfl_xor_sync(0xffffffffu, sm0, 1);
        sm0 += __shfl_xor_sync(0xffffffffu, sm0, 2);
        sm1 += __shfl_xor_sync(0xffffffffu, sm1, 1);
        sm1 += __shfl_xor_sync(0xffffffffu, sm1, 2);
        l0r = l0r * cr0 + sm0;
        l1r = l1r * cr1 + sm1;
        m0r = mn0; m1r = mn1;
#pragma unroll
        for (int j = 0; j < 8; j++) {
            o[j][0] *= cr0; o[j][1] *= cr0;
            o[j][2] *= cr1; o[j][3] *= cr1;
        }

        // ---- P -> fp16 hi/lo A-fragments (kept split: protects O) ----
        uint32_t ph[4][4], pl[4][4];
#pragma unroll
        for (int t = 0; t < 4; t++) {
            ph[t][0] = pack_f16x2(s[2 * t][1], s[2 * t][0]);
            ph[t][1] = pack_f16x2(s[2 * t][3], s[2 * t][2]);
            ph[t][2] = pack_f16x2(s[2 * t + 1][1], s[2 * t + 1][0]);
            ph[t][3] = pack_f16x2(s[2 * t + 1][3], s[2 * t + 1][2]);
            float2 u0 = unpack_f16x2(ph[t][0]);
            float2 u1 = unpack_f16x2(ph[t][1]);
            float2 u2 = unpack_f16x2(ph[t][2]);
            float2 u3 = unpack_f16x2(ph[t][3]);
            pl[t][0] = pack_f16x2(s[2 * t][1] - u0.y,     s[2 * t][0] - u0.x);
            pl[t][1] = pack_f16x2(s[2 * t][3] - u1.y,     s[2 * t][2] - u1.x);
            pl[t][2] = pack_f16x2(s[2 * t + 1][1] - u2.y, s[2 * t + 1][0] - u2.x);
            pl[t][3] = pack_f16x2(s[2 * t + 1][3] - u3.y, s[2 * t + 1][2] - u3.x);
        }

        // ---- O += (Ph+Pl) @ Vh ----
        const uint32_t vb = sb + AKT_B;
#pragma unroll
        for (int jp = 0; jp < 4; jp++) {
#pragma unroll
            for (int kc = 0; kc < 4; kc++) {
                const uint32_t aV = vb + (uint32_t)((
                    (kc * 16 + ((lid >> 3) & 1) * 8 + (lid & 7)) * 72 +
                    jp * 16 + (lid >> 4) * 8) * 2);
                uint32_t vh[4];
                ldm_x4_t(vh, aV);
                mma_f16(o[2 * jp],     ph[kc], &vh[0]);
                mma_f16(o[2 * jp + 1], ph[kc], &vh[2]);
                mma_f16(o[2 * jp],     pl[kc], &vh[0]);
                mma_f16(o[2 * jp + 1], pl[kc], &vh[2]);
            }
        }
    }
#undef ISSUE_KT

    // ---- epilogue: normalize, write ctx as fp16 hi ----
    const float inv0 = 1.f / l0r;
    const float inv1 = 1.f / l1r;
    const size_t r0 = (size_t)(bT0 + qrow0) * C_;
    const size_t r1 = (size_t)(bT0 + qrow1) * C_;
#pragma unroll
    for (int jn = 0; jn < 8; jn++) {
        const int col = h * 64 + jn * 8 + (lid & 3) * 2;
        float e0 = o[jn][0] * inv0, e1 = o[jn][1] * inv0;
        float e2 = o[jn][2] * inv1, e3 = o[jn][3] * inv1;
        *reinterpret_cast<uint32_t*>(&ch_g[r0 + col]) = pack_f16x2(e1, e0);
        *reinterpret_cast<uint32_t*>(&ch_g[r1 + col]) = pack_f16x2(e3, e2);
    }
}

// ---------------------------------------------------------------------------
// kernel_launch
// ---------------------------------------------------------------------------
extern "C" void kernel_launch(void* const* d_in, const int* in_sizes, int n_in,
                              void* d_out, int out_size)
{
    const float* x      = (const float*)d_in[0];  // [B,T,C]
    const float* w_qkv  = (const float*)d_in[1];  // [3C,C]
    const float* w_proj = (const float*)d_in[2];  // [C,C]
    float* out = (float*)d_out;                   // [B,T,C]

    __half *xh, *wqh, *wph, *qh, *ch;
    cudaGetSymbolAddress((void**)&xh,  g_xh);
    cudaGetSymbolAddress((void**)&wqh, g_wqh);
    cudaGetSymbolAddress((void**)&wph, g_wph);
    cudaGetSymbolAddress((void**)&qh,  g_qh);
    cudaGetSymbolAddress((void**)&ch,  g_ch);

    cudaFuncSetAttribute(gemm_mma_f16<true>,
                         cudaFuncAttributeMaxDynamicSharedMemorySize, GEMM_SMEM);
    cudaFuncSetAttribute(gemm_mma_f16<false>,
                         cudaFuncAttributeMaxDynamicSharedMemorySize, GEMM_SMEM);
    cudaFuncSetAttribute(attn_mma,
                         cudaFuncAttributeMaxDynamicSharedMemorySize, ATT_SMEM);

    // Fused convert (one launch)
    prep_f16<<<(PREP_JOBS + 255) / 256, 256>>>(x, w_qkv, w_proj, xh, wqh, wph);

    // 1) QKV projection (single-pass fp16) -> qh
    dim3 g1(QKV_N / 128, M_ / 128);
    gemm_mma_f16<true><<<g1, 256, GEMM_SMEM>>>(
        xh, wqh, nullptr, qh, M_, QKV_N, C_);

    // 2) Tensor-core causal flash attention -> ch (fp16)
    dim3 g2(T_ / 64, B_ * H_);
    attn_mma<<<g2, 128, ATT_SMEM>>>(qh, ch);

    // 3) Output projection (single-pass fp16) -> fp32 out
    dim3 g3(C_ / 128, M_ / 128);
    gemm_mma_f16<false><<<g3, 256, GEMM_SMEM>>>(
        ch, wph, out, nullptr, M_, C_, C_);
}

// round 14
// speedup vs baseline: 2.1277x; 1.0895x over previous
#include <cuda_runtime.h>
#include <cuda_fp16.h>
#include <cstdint>

// Problem constants
#define B_  4
#define T_  2048
#define C_  1024
#define H_  16
#define D_  64
#define M_  (B_ * T_)       // 8192 rows
#define QKV_N (3 * C_)      // 3072

// ---------------------------------------------------------------------------
// Scratch (device globals; no runtime allocation allowed)
// ---------------------------------------------------------------------------
__device__ __half g_xh[(size_t)M_ * C_];
__device__ __half g_wqh[(size_t)QKV_N * C_];
__device__ __half g_wph[(size_t)C_ * C_];
__device__ __half g_qh[(size_t)M_ * QKV_N];
__device__ __half g_ch[(size_t)M_ * C_];

// ---------------------------------------------------------------------------
// PTX helpers (all non-arch-gated sm_80/sm_90 instructions)
// ---------------------------------------------------------------------------
__device__ __forceinline__ uint32_t smem_u32(const void* p) {
    uint32_t a;
    asm("{ .reg .u64 t; cvta.to.shared.u64 t, %1; cvt.u32.u64 %0, t; }"
        : "=r"(a) : "l"(p));
    return a;
}
__device__ __forceinline__ void cp_async16(uint32_t s, const void* g) {
    asm volatile("cp.async.cg.shared.global [%0], [%1], 16;"
                 :: "r"(s), "l"(g) : "memory");
}
#define CP_COMMIT() asm volatile("cp.async.commit_group;" ::: "memory")
#define CP_WAIT0()  asm volatile("cp.async.wait_group 0;" ::: "memory")
#define CP_WAIT1()  asm volatile("cp.async.wait_group 1;" ::: "memory")

__device__ __forceinline__ void ldm_x4(uint32_t* r, uint32_t a) {
    asm volatile("ldmatrix.sync.aligned.m8n8.x4.shared.b16 {%0,%1,%2,%3}, [%4];"
        : "=r"(r[0]), "=r"(r[1]), "=r"(r[2]), "=r"(r[3]) : "r"(a));
}
__device__ __forceinline__ void ldm_x4_t(uint32_t* r, uint32_t a) {
    asm volatile("ldmatrix.sync.aligned.m8n8.x4.trans.shared.b16 {%0,%1,%2,%3}, [%4];"
        : "=r"(r[0]), "=r"(r[1]), "=r"(r[2]), "=r"(r[3]) : "r"(a));
}
__device__ __forceinline__ void mma_f16(float* d, const uint32_t* a, const uint32_t* b) {
    asm volatile(
        "mma.sync.aligned.m16n8k16.row.col.f32.f16.f16.f32 "
        "{%0,%1,%2,%3}, {%4,%5,%6,%7}, {%8,%9}, {%0,%1,%2,%3};"
        : "+f"(d[0]), "+f"(d[1]), "+f"(d[2]), "+f"(d[3])
        : "r"(a[0]), "r"(a[1]), "r"(a[2]), "r"(a[3]), "r"(b[0]), "r"(b[1]));
}
// pack two f32 -> f16x2 ({hi -> upper16, lo -> lower16})
__device__ __forceinline__ uint32_t pack_f16x2(float hi, float lo) {
    uint32_t d;
    asm("cvt.rn.f16x2.f32 %0, %1, %2;" : "=r"(d) : "f"(hi), "f"(lo));
    return d;
}

// ---------------------------------------------------------------------------
// Fused prep: convert x, w_qkv, w_proj to fp16 in ONE launch.
// ---------------------------------------------------------------------------
#define NX_JOBS  (M_ * C_ / 4)
#define NWQ_JOBS (QKV_N * C_ / 4)
#define NWP_JOBS (C_ * C_ / 4)
#define PREP_JOBS (NX_JOBS + NWQ_JOBS + NWP_JOBS)

__global__ __launch_bounds__(256) void prep_f16(
    const float* __restrict__ x, const float* __restrict__ wq,
    const float* __restrict__ wp,
    __half* __restrict__ xh, __half* __restrict__ wqh, __half* __restrict__ wph)
{
    int i = blockIdx.x * blockDim.x + threadIdx.x;
    if (i >= PREP_JOBS) return;
    const float* src;
    __half* dst;
    int j;
    if (i < NX_JOBS)                    { src = x;  dst = xh;  j = i; }
    else if (i < NX_JOBS + NWQ_JOBS)    { src = wq; dst = wqh; j = i - NX_JOBS; }
    else                                { src = wp; dst = wph; j = i - NX_JOBS - NWQ_JOBS; }
    float4 v = reinterpret_cast<const float4*>(src)[j];
    reinterpret_cast<uint2*>(dst)[j] =
        make_uint2(pack_f16x2(v.y, v.x), pack_f16x2(v.w, v.z));
}

// ---------------------------------------------------------------------------
// mma.sync fp16 GEMM: C[M,N] = Ah[M,K] @ Bh[N,K]^T (single pass).
// 128x128 CTA tile, BK=64, 8 warps (2x4), warp tile 64x32.
// 2-stage cp.async pipeline; 2 CTAs/SM. Stage = Ah | Bh (72-b16 rows).
// OUTH=true: write fp16; else fp32.
// ---------------------------------------------------------------------------
#define TILE_B  18432                   // 128 rows * 72 b16 * 2B
#define STAGE_B (2 * TILE_B)            // 36864
#define GEMM_SMEM (2 * STAGE_B)         // 73728 (x2 CTAs = 144KB <= 228KB)

template <bool OUTH>
__global__ __launch_bounds__(256, 2) void gemm_mma_f16(
    const __half* __restrict__ Ah, const __half* __restrict__ Bh,
    float* __restrict__ Cf, __half* __restrict__ Ch, int M, int N, int K)
{
    extern __shared__ char smc[];
    const uint32_t sbase = smem_u32(smc);
    const int tid = threadIdx.x;
    const int lid = tid & 31;
    const int wid = tid >> 5;
    const int wm  = wid >> 2;      // 0..1
    const int wn  = wid & 3;       // 0..3
    const int m0  = blockIdx.y * 128;
    const int n0  = blockIdx.x * 128;

    float acc[4][4][4];
#pragma unroll
    for (int i = 0; i < 4; i++)
#pragma unroll
        for (int j = 0; j < 4; j++)
#pragma unroll
            for (int q = 0; q < 4; q++) acc[i][j][q] = 0.f;

    // ldmatrix per-thread base offsets (b16 units within a tile, stride 72)
    const int a_base = (wm * 64 + (lid & 15)) * 72 + ((lid >> 4) * 8);
    // B paired-x4 mapping: matrices [n0k0, n0k1, n1k0, n1k1]
    const int b_base = (wn * 32 + (lid & 7) + ((lid >> 4) * 8)) * 72 +
                       (((lid >> 3) & 1) * 8);
    const int NS = K / 64;

#define ISSUE_STAGE(S)                                                          \
    do {                                                                        \
        const int _kc = (S) * 64;                                               \
        const uint32_t _sb = sbase + ((S) & 1) * STAGE_B;                       \
        _Pragma("unroll")                                                       \
        for (int _r = 0; _r < 4; _r++) {                                        \
            const int _c   = tid + _r * 256;      /* 0..1023 */                 \
            const int _row = _c >> 3;             /* 0..127  */                 \
            const int _c8  = (_c & 7) * 8;        /* 0..56   */                 \
            const uint32_t _so = _sb + (uint32_t)((_row * 72 + _c8) * 2);       \
            cp_async16(_so,          Ah + (size_t)(m0 + _row) * K + _kc + _c8); \
            cp_async16(_so + TILE_B, Bh + (size_t)(n0 + _row) * K + _kc + _c8); \
        }                                                                       \
        CP_COMMIT();                                                            \
    } while (0)

    ISSUE_STAGE(0);

    for (int s = 0; s < NS; s++) {
        CP_WAIT0();
        __syncthreads();
        if (s + 1 < NS) ISSUE_STAGE(s + 1);

        const uint32_t sb = sbase + (s & 1) * STAGE_B;
#pragma unroll
        for (int ks = 0; ks < 4; ks++) {
            uint32_t ah[4][4], b01[4], b23[4];
#pragma unroll
            for (int mi = 0; mi < 4; mi++) {
                const uint32_t ao = sb +
                    (uint32_t)((a_base + mi * 16 * 72 + ks * 16) * 2);
                ldm_x4(ah[mi], ao);
            }
            {
                const uint32_t bo = sb + TILE_B +
                    (uint32_t)((b_base + ks * 16) * 2);
                ldm_x4(b01, bo);                       // n-chunks 0,1
                ldm_x4(b23, bo + 16 * 72 * 2);         // n-chunks 2,3
            }
#pragma unroll
            for (int mi = 0; mi < 4; mi++) {
                mma_f16(acc[mi][0], ah[mi], &b01[0]);
                mma_f16(acc[mi][1], ah[mi], &b01[2]);
                mma_f16(acc[mi][2], ah[mi], &b23[0]);
                mma_f16(acc[mi][3], ah[mi], &b23[2]);
            }
        }
    }
#undef ISSUE_STAGE

#pragma unroll
    for (int mi = 0; mi < 4; mi++)
#pragma unroll
        for (int ni = 0; ni < 4; ni++) {
            const int row = m0 + wm * 64 + mi * 16 + (lid >> 2);
            const int col = n0 + wn * 32 + ni * 8 + (lid & 3) * 2;
            if (OUTH) {
                uint32_t h0 = pack_f16x2(acc[mi][ni][1], acc[mi][ni][0]);
                uint32_t h1 = pack_f16x2(acc[mi][ni][3], acc[mi][ni][2]);
                *reinterpret_cast<uint32_t*>(&Ch[(size_t)row * N + col])       = h0;
                *reinterpret_cast<uint32_t*>(&Ch[(size_t)(row + 8) * N + col]) = h1;
            } else {
                float2 v0 = make_float2(acc[mi][ni][0], acc[mi][ni][1]);
                float2 v1 = make_float2(acc[mi][ni][2], acc[mi][ni][3]);
                *reinterpret_cast<float2*>(&Cf[(size_t)row * N + col])       = v0;
                *reinterpret_cast<float2*>(&Cf[(size_t)(row + 8) * N + col]) = v1;
            }
        }
}

// ---------------------------------------------------------------------------
// Tensor-core causal flash attention, pure fp16 operands.
// Q, K, V, P all consumed as rounded fp16; accumulators fp32.
// CTA: 128 thr (4 warps), 64-row Q tile per CTA -> 4 CTAs/SM.
// K/V 64-row tiles, 3-stage cp.async pipeline. Softmax in log2 domain.
// ---------------------------------------------------------------------------
#define AKT_B   9216                 // 64 rows * 72 b16 * 2B
#define ASTG_B  (2 * AKT_B)          // Kh | Vh
#define ATT_SMEM (3 * ASTG_B)        // 55296 (x4 CTAs = 216KB <= 228KB)
#define SCALE_L2E 0.1803368801111204f   // 0.125 * log2(e)

__global__ __launch_bounds__(128, 4) void attn_mma(
    const __half* __restrict__ qh_g, __half* __restrict__ ch_g)
{
    extern __shared__ char smc[];
    const uint32_t abase = smem_u32(smc);
    const int tid = threadIdx.x;
    const int lid = tid & 31;
    const int wid = tid >> 5;
    const int qi  = (int)gridDim.x - 1 - (int)blockIdx.x;  // long CTAs first
    const int bh  = blockIdx.y;
    const int b   = bh >> 4;
    const int h   = bh & 15;
    const int q0  = qi * 64;
    const int bT0 = b * T_;
    const int nkt = qi + 1;

    // ---- Q fragments (fp16), loaded once from global ----
    uint32_t qfh[4][4];
    {
        const int r0 = bT0 + q0 + wid * 16 + (lid >> 2);
#pragma unroll
        for (int kc = 0; kc < 4; kc++) {
            const int c0 = h * 64 + kc * 16 + (lid & 3) * 2;
            const size_t o00 = (size_t)r0 * QKV_N + c0;
            const size_t o10 = o00 + 8 * QKV_N;
            qfh[kc][0] = *reinterpret_cast<const uint32_t*>(qh_g + o00);
            qfh[kc][1] = *reinterpret_cast<const uint32_t*>(qh_g + o10);
            qfh[kc][2] = *reinterpret_cast<const uint32_t*>(qh_g + o00 + 8);
            qfh[kc][3] = *reinterpret_cast<const uint32_t*>(qh_g + o10 + 8);
        }
    }

    float o[8][4];
#pragma unroll
    for (int j = 0; j < 8; j++)
#pragma unroll
        for (int q = 0; q < 4; q++) o[j][q] = 0.f;
    float m0r = -1e30f, m1r = -1e30f, l0r = 0.f, l1r = 0.f;

    // K/V tile loader: 2 tiles x 64 rows x 8 groups = 1024 jobs / 128 thr
#define ISSUE_KT(KT)                                                            \
    do {                                                                        \
        const uint32_t _sb = abase + ((KT) % 3) * ASTG_B;                       \
        const int _kv0 = (KT) * 64;                                             \
        _Pragma("unroll")                                                       \
        for (int _r = 0; _r < 8; _r++) {                                        \
            const int _j    = tid + _r * 128;                                   \
            const int _tile = _j >> 9;                                          \
            const int _rem  = _j & 511;                                         \
            const int _row  = _rem >> 3;                                        \
            const int _g    = _rem & 7;                                         \
            const size_t _go = (size_t)(bT0 + _kv0 + _row) * QKV_N              \
                               + C_ * (1 + _tile) + h * 64 + _g * 8;            \
            cp_async16(_sb + _tile * AKT_B + (uint32_t)(_row * 144 + _g * 16),  \
                       qh_g + _go);                                             \
        }                                                                       \
        CP_COMMIT();                                                            \
    } while (0)

    ISSUE_KT(0);
    if (nkt > 1) ISSUE_KT(1);

    const int qrow0 = q0 + wid * 16 + (lid >> 2);   // global q row (half 0)
    const int qrow1 = qrow0 + 8;

    for (int kt = 0; kt < nkt; kt++) {
        if (kt < nkt - 1) CP_WAIT1();
        else              CP_WAIT0();
        __syncthreads();
        if (kt + 2 < nkt) ISSUE_KT(kt + 2);

        const uint32_t sb = abase + (kt % 3) * ASTG_B;
        const int kv0 = kt * 64;

        // ---- S = Qh @ Kh^T ----
        float s[8][4];
#pragma unroll
        for (int jn = 0; jn < 8; jn++) {
#pragma unroll
            for (int q = 0; q < 4; q++) s[jn][q] = 0.f;
            const uint32_t aK = sb +
                (uint32_t)(((jn * 8 + (lid & 7)) * 72 + (lid >> 3) * 8) * 2);
            uint32_t khA[4], khB[4];
            ldm_x4(khA, aK);
            ldm_x4(khB, aK + 64);
            mma_f16(s[jn], qfh[0], &khA[0]);
            mma_f16(s[jn], qfh[1], &khA[2]);
            mma_f16(s[jn], qfh[2], &khB[0]);
            mma_f16(s[jn], qfh[3], &khB[2]);
        }

        // scale (log2 domain) + causal mask (diagonal ktile only)
        const bool need_mask = (kt == nkt - 1);
#pragma unroll
        for (int jn = 0; jn < 8; jn++) {
#pragma unroll
            for (int q = 0; q < 4; q++) s[jn][q] *= SCALE_L2E;
            if (need_mask) {
                const int c = kv0 + jn * 8 + (lid & 3) * 2;
                if (c > qrow0)     s[jn][0] = -1e30f;
                if (c + 1 > qrow0) s[jn][1] = -1e30f;
                if (c > qrow1)     s[jn][2] = -1e30f;
                if (c + 1 > qrow1) s[jn][3] = -1e30f;
            }
        }

        // ---- online softmax in log2 domain (rows qrow0, qrow1) ----
        float mx0 = s[0][0], mx1 = s[0][2];
#pragma unroll
        for (int jn = 0; jn < 8; jn++) {
            mx0 = fmaxf(mx0, fmaxf(s[jn][0], s[jn][1]));
            mx1 = fmaxf(mx1, fmaxf(s[jn][2], s[jn][3]));
        }
        mx0 = fmaxf(mx0, __shfl_xor_sync(0xffffffffu, mx0, 1));
        mx0 = fmaxf(mx0, __shfl_xor_sync(0xffffffffu, mx0, 2));
        mx1 = fmaxf(mx1, __shfl_xor_sync(0xffffffffu, mx1, 1));
        mx1 = fmaxf(mx1, __shfl_xor_sync(0xffffffffu, mx1, 2));
        const float mn0 = fmaxf(m0r, mx0);
        const float mn1 = fmaxf(m1r, mx1);
        const float cr0 = exp2f(m0r - mn0);
        const float cr1 = exp2f(m1r - mn1);
        float sm0 = 0.f, sm1 = 0.f;
#pragma unroll
        for (int jn = 0; jn < 8; jn++) {
            s[jn][0] = exp2f(s[jn][0] - mn0);
            s[jn][1] = exp2f(s[jn][1] - mn0);
            s[jn][2] = exp2f(s[jn][2] - mn1);
            s[jn][3] = exp2f(s[jn][3] - mn1);
            sm0 += s[jn][0] + s[jn][1];
            sm1 += s[jn][2] + s[jn][3];
        }
        sm0 += __shfl_xor_sync(0xffffffffu, sm0, 1);
        sm0 += __shfl_xor_sync(0xffffffffu, sm0, 2);
        sm1 += __shfl_xor_sync(0xffffffffu, sm1, 1);
        sm1 += __shfl_xor_sync(0xffffffffu, sm1, 2);
        l0r = l0r * cr0 + sm0;
        l1r = l1r * cr1 + sm1;
        m0r = mn0; m1r = mn1;
#pragma unroll
        for (int j = 0; j < 8; j++) {
            o[j][0] *= cr0; o[j][1] *= cr0;
            o[j][2] *= cr1; o[j][3] *= cr1;
        }

        // ---- P -> fp16 A-fragments (single rounding; Pl dropped) ----
        uint32_t ph[4][4];
#pragma unroll
        for (int t = 0; t < 4; t++) {
            ph[t][0] = pack_f16x2(s[2 * t][1], s[2 * t][0]);
            ph[t][1] = pack_f16x2(s[2 * t][3], s[2 * t][2]);
            ph[t][2] = pack_f16x2(s[2 * t + 1][1], s[2 * t + 1][0]);
            ph[t][3] = pack_f16x2(s[2 * t + 1][3], s[2 * t + 1][2]);
        }

        // ---- O += Ph @ Vh ----
        const uint32_t vb = sb + AKT_B;
#pragma unroll
        for (int jp = 0; jp < 4; jp++) {
#pragma unroll
            for (int kc = 0; kc < 4; kc++) {
                const uint32_t aV = vb + (uint32_t)((
                    (kc * 16 + ((lid >> 3) & 1) * 8 + (lid & 7)) * 72 +
                    jp * 16 + (lid >> 4) * 8) * 2);
                uint32_t vh[4];
                ldm_x4_t(vh, aV);
                mma_f16(o[2 * jp],     ph[kc], &vh[0]);
                mma_f16(o[2 * jp + 1], ph[kc], &vh[2]);
            }
        }
    }
#undef ISSUE_KT

    // ---- epilogue: normalize, write ctx as fp16 ----
    const float inv0 = 1.f / l0r;
    const float inv1 = 1.f / l1r;
    const size_t r0 = (size_t)(bT0 + qrow0) * C_;
    const size_t r1 = (size_t)(bT0 + qrow1) * C_;
#pragma unroll
    for (int jn = 0; jn < 8; jn++) {
        const int col = h * 64 + jn * 8 + (lid & 3) * 2;
        float e0 = o[jn][0] * inv0, e1 = o[jn][1] * inv0;
        float e2 = o[jn][2] * inv1, e3 = o[jn][3] * inv1;
        *reinterpret_cast<uint32_t*>(&ch_g[r0 + col]) = pack_f16x2(e1, e0);
        *reinterpret_cast<uint32_t*>(&ch_g[r1 + col]) = pack_f16x2(e3, e2);
    }
}

// ---------------------------------------------------------------------------
// kernel_launch
// ---------------------------------------------------------------------------
extern "C" void kernel_launch(void* const* d_in, const int* in_sizes, int n_in,
                              void* d_out, int out_size)
{
    const float* x      = (const float*)d_in[0];  // [B,T,C]
    const float* w_qkv  = (const float*)d_in[1];  // [3C,C]
    const float* w_proj = (const float*)d_in[2];  // [C,C]
    float* out = (float*)d_out;                   // [B,T,C]

    __half *xh, *wqh, *wph, *qh, *ch;
    cudaGetSymbolAddress((void**)&xh,  g_xh);
    cudaGetSymbolAddress((void**)&wqh, g_wqh);
    cudaGetSymbolAddress((void**)&wph, g_wph);
    cudaGetSymbolAddress((void**)&qh,  g_qh);
    cudaGetSymbolAddress((void**)&ch,  g_ch);

    cudaFuncSetAttribute(gemm_mma_f16<true>,
                         cudaFuncAttributeMaxDynamicSharedMemorySize, GEMM_SMEM);
    cudaFuncSetAttribute(gemm_mma_f16<false>,
                         cudaFuncAttributeMaxDynamicSharedMemorySize, GEMM_SMEM);
    cudaFuncSetAttribute(attn_mma,
                         cudaFuncAttributeMaxDynamicSharedMemorySize, ATT_SMEM);

    // Fused convert (one launch)
    prep_f16<<<(PREP_JOBS + 255) / 256, 256>>>(x, w_qkv, w_proj, xh, wqh, wph);

    // 1) QKV projection (single-pass fp16) -> qh
    dim3 g1(QKV_N / 128, M_ / 128);
    gemm_mma_f16<true><<<g1, 256, GEMM_SMEM>>>(
        xh, wqh, nullptr, qh, M_, QKV_N, C_);

    // 2) Tensor-core causal flash attention -> ch (fp16)
    dim3 g2(T_ / 64, B_ * H_);
    attn_mma<<<g2, 128, ATT_SMEM>>>(qh, ch);

    // 3) Output projection (single-pass fp16) -> fp32 out
    dim3 g3(C_ / 128, M_ / 128);
    gemm_mma_f16<false><<<g3, 256, GEMM_SMEM>>>(
        ch, wph, out, nullptr, M_, C_, C_);
}